// round 5
// baseline (speedup 1.0000x reference)
#include <cuda_runtime.h>

#define NT    8192
#define KT    200
#define CINC  512
#define HIDC  256
#define COUTC 40
#define EE    5
#define MHD   64
#define TGRID 4096
#define TBL_LO (-8.0f)
#define TBL_HI ( 8.0f)
#define PA 72      // A smem pitch (64 + 8)  -> t4*8+g banks, conflict-free frags
#define PB 136     // B smem pitch (128 + 8)
#define SMEM_G ((2 * 16 * PA * 2 + 2 * 16 * PB * 2) * 4)   // 53248 B

// ---------------- scratch ----------------
__device__ float d_ftable[EE * TGRID];
__device__ float d_Vsum[KT];
__device__ float d_Tm[KT * CINC];       // T = U^T X   [200 x 512]
__device__ float d_P[KT * HIDC];        // P = T @ Ww  [200 x 256]
__device__ float d_colsum[HIDC], d_colsq[HIDC];

__device__ __forceinline__ unsigned f2tf32(float x) {
    unsigned r;
    asm("cvt.rna.tf32.f32 %0, %1;" : "=r"(r) : "f"(x));
    return r;
}

__device__ __forceinline__ void mma_tf32(float* c, const unsigned* a, const unsigned* b) {
    asm volatile(
        "mma.sync.aligned.m16n8k8.row.col.f32.tf32.tf32.f32 "
        "{%0,%1,%2,%3},{%4,%5,%6,%7},{%8,%9},{%0,%1,%2,%3};"
        : "+f"(c[0]), "+f"(c[1]), "+f"(c[2]), "+f"(c[3])
        : "r"(a[0]), "r"(a[1]), "r"(a[2]), "r"(a[3]), "r"(b[0]), "r"(b[1]));
}

__device__ __forceinline__ float pwl(const float* __restrict__ tbl, float u, float scale) {
    float xi = (u - TBL_LO) * scale;
    xi = fminf(fmaxf(xi, 0.f), (float)(TGRID - 2) + 0.9999f);
    int   i  = (int)xi;
    float fr = xi - (float)i;
    float a = tbl[i], b = tbl[i + 1];
    return fmaf(fr, b - a, a);
}

// ---------------- zero accumulators ----------------
__global__ void k_zero() {
    int i = blockIdx.x * blockDim.x + threadIdx.x;
    if (i < KT * CINC) d_Tm[i] = 0.f;
    if (i < KT * HIDC) d_P[i] = 0.f;
    if (i < KT) d_Vsum[i] = 0.f;
    if (i < HIDC) { d_colsum[i] = 0.f; d_colsq[i] = 0.f; }
}

// ---------------- per-expert PWL tables ----------------
__global__ void k_table(const float* __restrict__ eW1, const float* __restrict__ eb1,
                        const float* __restrict__ eW2, const float* __restrict__ eb2,
                        const float* __restrict__ eW3, const float* __restrict__ eb3) {
    int e = blockIdx.y;
    __shared__ float W2s[MHD * MHD];
    __shared__ float W1s[MHD], b1s[MHD], b2s[MHD], W3s[MHD];
    for (int i = threadIdx.x; i < MHD * MHD; i += blockDim.x) W2s[i] = eW2[e * MHD * MHD + i];
    if (threadIdx.x < MHD) {
        W1s[threadIdx.x] = eW1[e * MHD + threadIdx.x];
        b1s[threadIdx.x] = eb1[e * MHD + threadIdx.x];
        b2s[threadIdx.x] = eb2[e * MHD + threadIdx.x];
        W3s[threadIdx.x] = eW3[e * MHD + threadIdx.x];
    }
    __syncthreads();

    int t = blockIdx.x * blockDim.x + threadIdx.x;
    float x = TBL_LO + (TBL_HI - TBL_LO) * ((float)t / (float)(TGRID - 1));

    float h1[MHD];
#pragma unroll
    for (int h = 0; h < MHD; h++) h1[h] = fmaxf(fmaf(x, W1s[h], b1s[h]), 0.f);

    float v = eb3[e];
    for (int j = 0; j < MHD; j += 4) {
        float a0 = b2s[j], a1 = b2s[j + 1], a2 = b2s[j + 2], a3 = b2s[j + 3];
#pragma unroll
        for (int h = 0; h < MHD; h++) {
            float hv = h1[h];
            float4 w = *(const float4*)&W2s[h * MHD + j];
            a0 = fmaf(hv, w.x, a0);
            a1 = fmaf(hv, w.y, a1);
            a2 = fmaf(hv, w.z, a2);
            a3 = fmaf(hv, w.w, a3);
        }
        v = fmaf(fmaxf(a0, 0.f), W3s[j],     v);
        v = fmaf(fmaxf(a1, 0.f), W3s[j + 1], v);
        v = fmaf(fmaxf(a2, 0.f), W3s[j + 2], v);
        v = fmaf(fmaxf(a3, 0.f), W3s[j + 3], v);
    }
    d_ftable[e * TGRID + t] = v;
}

// ============ T = U^T @ X  (3xtf32, 64x128 tile, 2 CTA/SM, fused reduceV) ============
// grid (4 Mtiles, 4 Ntiles, 32 Kchunks of 256 rows)
__global__ void __launch_bounds__(256, 2) k_gemmT3(const float* __restrict__ U,
                                                   const float* __restrict__ X) {
    extern __shared__ unsigned smemb[];
    unsigned* AhB = smemb;
    unsigned* AlB = AhB + 2 * 16 * PA;
    unsigned* BhB = AlB + 2 * 16 * PA;
    unsigned* BlB = BhB + 2 * 16 * PB;

    int m0 = blockIdx.x * 64;
    int n0 = blockIdx.y * 128;
    int zbase = blockIdx.z * 256;
    int tid = threadIdx.x;
    int w = tid >> 5, lane = tid & 31, g = lane >> 2, t4 = lane & 3;
    int wm = w & 1, wn = w >> 1;
    int alm = tid & 63,  alr = tid >> 6;
    int blm = tid & 127, blr = tid >> 7;
    int gm = m0 + alm;
    bool mok = gm < KT;
    bool doV = (blockIdx.y == 0) && mok;
    const float* tbl = d_ftable + ((mok ? gm : 0) / 40) * TGRID;
    const float vscale = (float)(TGRID - 1) / (TBL_HI - TBL_LO);
    float vloc = 0.f;

    float C[2][4][4];
#pragma unroll
    for (int i = 0; i < 2; i++)
#pragma unroll
        for (int j = 0; j < 4; j++) { C[i][j][0] = C[i][j][1] = C[i][j][2] = C[i][j][3] = 0.f; }

    float uA[4], xA[8], uB[4], xB[8];
#pragma unroll
    for (int l = 0; l < 4; l++) uA[l] = mok ? U[(zbase + alr + 4 * l) * KT + gm] : 0.f;
#pragma unroll
    for (int l = 0; l < 8; l++) xA[l] = X[(zbase + blr + 2 * l) * CINC + n0 + blm];
    if (doV) {
#pragma unroll
        for (int l = 0; l < 4; l++) vloc += pwl(tbl, uA[l], vscale);
    }
    {   // store stage 0
#pragma unroll
        for (int l = 0; l < 4; l++) {
            int r = alr + 4 * l;
            unsigned hi = f2tf32(uA[l]);
            AhB[r * PA + alm] = hi;
            AlB[r * PA + alm] = f2tf32(uA[l] - __uint_as_float(hi));
        }
#pragma unroll
        for (int l = 0; l < 8; l++) {
            int r = blr + 2 * l;
            unsigned hi = f2tf32(xA[l]);
            BhB[r * PB + blm] = hi;
            BlB[r * PB + blm] = f2tf32(xA[l] - __uint_as_float(hi));
        }
    }
    __syncthreads();

    for (int kt = 0; kt < 16; kt++) {
        int p = kt & 1;
        const unsigned* AhP = AhB + p * 16 * PA;
        const unsigned* AlP = AlB + p * 16 * PA;
        const unsigned* BhP = BhB + p * 16 * PB;
        const unsigned* BlP = BlB + p * 16 * PB;
        if (kt < 15) {
            int nb = zbase + (kt + 1) * 16;
#pragma unroll
            for (int l = 0; l < 4; l++) uB[l] = mok ? U[(nb + alr + 4 * l) * KT + gm] : 0.f;
#pragma unroll
            for (int l = 0; l < 8; l++) xB[l] = X[(nb + blr + 2 * l) * CINC + n0 + blm];
            if (doV) {
#pragma unroll
                for (int l = 0; l < 4; l++) vloc += pwl(tbl, uB[l], vscale);
            }
        }
#pragma unroll
        for (int ks = 0; ks < 16; ks += 8) {
            unsigned bh[4][2], bl[4][2];
#pragma unroll
            for (int ni = 0; ni < 4; ni++) {
                int cn = wn * 32 + ni * 8;
                bh[ni][0] = BhP[(ks + t4) * PB + cn + g];
                bh[ni][1] = BhP[(ks + t4 + 4) * PB + cn + g];
                bl[ni][0] = BlP[(ks + t4) * PB + cn + g];
                bl[ni][1] = BlP[(ks + t4 + 4) * PB + cn + g];
            }
#pragma unroll
            for (int mi = 0; mi < 2; mi++) {
                int rm = wm * 32 + mi * 16;
                unsigned ah[4], al[4];
                ah[0] = AhP[(ks + t4) * PA + rm + g];     ah[1] = AhP[(ks + t4) * PA + rm + g + 8];
                ah[2] = AhP[(ks + t4 + 4) * PA + rm + g]; ah[3] = AhP[(ks + t4 + 4) * PA + rm + g + 8];
                al[0] = AlP[(ks + t4) * PA + rm + g];     al[1] = AlP[(ks + t4) * PA + rm + g + 8];
                al[2] = AlP[(ks + t4 + 4) * PA + rm + g]; al[3] = AlP[(ks + t4 + 4) * PA + rm + g + 8];
#pragma unroll
                for (int ni = 0; ni < 4; ni++) {
                    mma_tf32(C[mi][ni], ah, bl[ni]);
                    mma_tf32(C[mi][ni], al, bh[ni]);
                    mma_tf32(C[mi][ni], ah, bh[ni]);
                }
            }
        }
        if (kt < 15) {
            unsigned* AhQ = AhB + (p ^ 1) * 16 * PA;
            unsigned* AlQ = AlB + (p ^ 1) * 16 * PA;
            unsigned* BhQ = BhB + (p ^ 1) * 16 * PB;
            unsigned* BlQ = BlB + (p ^ 1) * 16 * PB;
#pragma unroll
            for (int l = 0; l < 4; l++) {
                int r = alr + 4 * l;
                unsigned hi = f2tf32(uB[l]);
                AhQ[r * PA + alm] = hi;
                AlQ[r * PA + alm] = f2tf32(uB[l] - __uint_as_float(hi));
            }
#pragma unroll
            for (int l = 0; l < 8; l++) {
                int r = blr + 2 * l;
                unsigned hi = f2tf32(xB[l]);
                BhQ[r * PB + blm] = hi;
                BlQ[r * PB + blm] = f2tf32(xB[l] - __uint_as_float(hi));
            }
        }
        __syncthreads();
    }
#pragma unroll
    for (int mi = 0; mi < 2; mi++) {
        int r = m0 + wm * 32 + mi * 16 + g;
#pragma unroll
        for (int ni = 0; ni < 4; ni++) {
            int c = n0 + wn * 32 + ni * 8 + 2 * t4;
            if (r < KT) {
                atomicAdd(&d_Tm[r * CINC + c],     C[mi][ni][0]);
                atomicAdd(&d_Tm[r * CINC + c + 1], C[mi][ni][1]);
            }
            if (r + 8 < KT) {
                atomicAdd(&d_Tm[(r + 8) * CINC + c],     C[mi][ni][2]);
                atomicAdd(&d_Tm[(r + 8) * CINC + c + 1], C[mi][ni][3]);
            }
        }
    }
    if (doV) atomicAdd(&d_Vsum[gm], vloc);
}

// ============ P = T @ Ww  [200 x 256]  (fp32, split-K atomics) ============
__global__ void __launch_bounds__(256) k_gemmP(const float* __restrict__ Ww) {
    __shared__ float As[32][17];
    __shared__ float Bs[16][64];
    int n0 = blockIdx.x * 64;
    int m0 = blockIdx.y * 32;
    int k0 = blockIdx.z * 128;
    int tid = threadIdx.x;
    int ty = tid >> 6, tx = tid & 63;
    float acc[8] = {};

    for (int kc = 0; kc < 128; kc += 16) {
#pragma unroll
        for (int l = 0; l < 2; l++) {
            int idx = tid + 256 * l;
            int r = idx >> 4, kk = idx & 15;
            As[r][kk] = (m0 + r < KT) ? d_Tm[(m0 + r) * CINC + k0 + kc + kk] : 0.f;
        }
#pragma unroll
        for (int l = 0; l < 4; l++) {
            int idx = tid + 256 * l;
            int kk = idx >> 6, n = idx & 63;
            Bs[kk][n] = Ww[(k0 + kc + kk) * HIDC + n0 + n];
        }
        __syncthreads();
#pragma unroll
        for (int kk = 0; kk < 16; kk++) {
            float b = Bs[kk][tx];
#pragma unroll
            for (int i = 0; i < 8; i++)
                acc[i] = fmaf(As[ty + 4 * i][kk], b, acc[i]);
        }
        __syncthreads();
    }
#pragma unroll
    for (int i = 0; i < 8; i++) {
        int r = m0 + ty + 4 * i;
        if (r < KT) atomicAdd(&d_P[r * HIDC + n0 + tx], acc[i]);
    }
}

// ============ hidden = (U*s)@P + Wb  (3xtf32, 64x128 tile, gate + BN fused) ============
// grid (128 Mtiles, 2 Ntiles)
__global__ void __launch_bounds__(256, 2) k_gemmH3(const float* __restrict__ U,
                                                   const float* __restrict__ La,
                                                   const float* __restrict__ gW1, const float* __restrict__ gb1,
                                                   const float* __restrict__ gW2, const float* __restrict__ gb2,
                                                   const float* __restrict__ Wb,
                                                   float* __restrict__ hid) {
    extern __shared__ unsigned smemb[];
    unsigned* AhB = smemb;
    unsigned* AlB = AhB + 2 * 16 * PA;
    unsigned* BhB = AlB + 2 * 16 * PA;
    unsigned* BlB = BhB + 2 * 16 * PB;
    __shared__ float sS[128], sQ[128];
    __shared__ float s_sm[KT + 16];
    __shared__ float stats[EE], gsh[EE];

    int m0 = blockIdx.x * 64;
    int n0 = blockIdx.y * 128;
    int tid = threadIdx.x;
    int w = tid >> 5, lane = tid & 31, g = lane >> 2, t4 = lane & 3;
    int wm = w & 1, wn = w >> 1;
    int ak = tid & 15, am = tid >> 4;
    int bm = tid & 127, br = tid >> 7;

    // ---- fused gate -> s_sm[0..199] ----
    if (tid < 128) { sS[tid] = 0.f; sQ[tid] = 0.f; }
    if (tid < KT + 16) s_sm[tid] = 0.f;
    __syncthreads();
    if (tid < EE) {
        float s = 0.f;
        for (int i = 0; i < 40; i++) s += La[tid * 40 + i];
        stats[tid] = s * (1.f / 40.f);
    }
    __syncthreads();
    if (tid == 0) {
        float h[EE], g2[EE];
        for (int j = 0; j < EE; j++) {
            float a = gb1[j];
            for (int i = 0; i < EE; i++) a = fmaf(stats[i], gW1[i * EE + j], a);
            h[j] = fmaxf(a, 0.f);
        }
        for (int j = 0; j < EE; j++) {
            float a = gb2[j];
            for (int i = 0; i < EE; i++) a = fmaf(h[i], gW2[i * EE + j], a);
            g2[j] = a;
        }
        float m = g2[0];
        for (int j = 1; j < EE; j++) m = fmaxf(m, g2[j]);
        float se = 0.f;
        for (int j = 0; j < EE; j++) { g2[j] = expf(g2[j] - m); se += g2[j]; }
        for (int j = 0; j < EE; j++) gsh[j] = g2[j] / se;
    }
    __syncthreads();
    if (tid < KT) s_sm[tid] = gsh[tid / 40] * d_Vsum[tid] * (1.f / (float)NT);
    __syncthreads();

    float C[2][4][4];
#pragma unroll
    for (int i = 0; i < 2; i++)
#pragma unroll
        for (int j = 0; j < 4; j++) { C[i][j][0] = C[i][j][1] = C[i][j][2] = C[i][j][3] = 0.f; }

    float aA[4], bA[8], aB[4], bB[8];
#pragma unroll
    for (int l = 0; l < 4; l++)
        aA[l] = U[(m0 + am + 16 * l) * KT + ak] * s_sm[ak];
#pragma unroll
    for (int l = 0; l < 8; l++) {
        int r = br + 2 * l;
        bA[l] = d_P[r * HIDC + n0 + bm];
    }
    {   // store stage 0
#pragma unroll
        for (int l = 0; l < 4; l++) {
            int m = am + 16 * l;
            unsigned hi = f2tf32(aA[l]);
            AhB[ak * PA + m] = hi;
            AlB[ak * PA + m] = f2tf32(aA[l] - __uint_as_float(hi));
        }
#pragma unroll
        for (int l = 0; l < 8; l++) {
            int r = br + 2 * l;
            unsigned hi = f2tf32(bA[l]);
            BhB[r * PB + bm] = hi;
            BlB[r * PB + bm] = f2tf32(bA[l] - __uint_as_float(hi));
        }
    }
    __syncthreads();

    for (int kt = 0; kt < 13; kt++) {
        int p = kt & 1;
        const unsigned* AhP = AhB + p * 16 * PA;
        const unsigned* AlP = AlB + p * 16 * PA;
        const unsigned* BhP = BhB + p * 16 * PB;
        const unsigned* BlP = BlB + p * 16 * PB;
        if (kt < 12) {
            int kb2 = (kt + 1) * 16;
            int kk = kb2 + ak;
            float sv = (kk < KT) ? s_sm[kk] : 0.f;
#pragma unroll
            for (int l = 0; l < 4; l++)
                aB[l] = (kk < KT) ? U[(m0 + am + 16 * l) * KT + kk] * sv : 0.f;
#pragma unroll
            for (int l = 0; l < 8; l++) {
                int r = kb2 + br + 2 * l;
                bB[l] = (r < KT) ? d_P[r * HIDC + n0 + bm] : 0.f;
            }
        }
#pragma unroll
        for (int ks = 0; ks < 16; ks += 8) {
            unsigned bh[4][2], bl[4][2];
#pragma unroll
            for (int ni = 0; ni < 4; ni++) {
                int cn = wn * 32 + ni * 8;
                bh[ni][0] = BhP[(ks + t4) * PB + cn + g];
                bh[ni][1] = BhP[(ks + t4 + 4) * PB + cn + g];
                bl[ni][0] = BlP[(ks + t4) * PB + cn + g];
                bl[ni][1] = BlP[(ks + t4 + 4) * PB + cn + g];
            }
#pragma unroll
            for (int mi = 0; mi < 2; mi++) {
                int rm = wm * 32 + mi * 16;
                unsigned ah[4], al[4];
                ah[0] = AhP[(ks + t4) * PA + rm + g];     ah[1] = AhP[(ks + t4) * PA + rm + g + 8];
                ah[2] = AhP[(ks + t4 + 4) * PA + rm + g]; ah[3] = AhP[(ks + t4 + 4) * PA + rm + g + 8];
                al[0] = AlP[(ks + t4) * PA + rm + g];     al[1] = AlP[(ks + t4) * PA + rm + g + 8];
                al[2] = AlP[(ks + t4 + 4) * PA + rm + g]; al[3] = AlP[(ks + t4 + 4) * PA + rm + g + 8];
#pragma unroll
                for (int ni = 0; ni < 4; ni++) {
                    mma_tf32(C[mi][ni], ah, bl[ni]);
                    mma_tf32(C[mi][ni], al, bh[ni]);
                    mma_tf32(C[mi][ni], ah, bh[ni]);
                }
            }
        }
        if (kt < 12) {
            unsigned* AhQ = AhB + (p ^ 1) * 16 * PA;
            unsigned* AlQ = AlB + (p ^ 1) * 16 * PA;
            unsigned* BhQ = BhB + (p ^ 1) * 16 * PB;
            unsigned* BlQ = BlB + (p ^ 1) * 16 * PB;
#pragma unroll
            for (int l = 0; l < 4; l++) {
                int m = am + 16 * l;
                unsigned hi = f2tf32(aB[l]);
                AhQ[ak * PA + m] = hi;
                AlQ[ak * PA + m] = f2tf32(aB[l] - __uint_as_float(hi));
            }
#pragma unroll
            for (int l = 0; l < 8; l++) {
                int r = br + 2 * l;
                unsigned hi = f2tf32(bB[l]);
                BhQ[r * PB + bm] = hi;
                BlQ[r * PB + bm] = f2tf32(bB[l] - __uint_as_float(hi));
            }
        }
        __syncthreads();
    }
    // epilogue: +Wb, store, BN partial sums
    float ls[8] = {}, lq[8] = {};
#pragma unroll
    for (int mi = 0; mi < 2; mi++) {
        int r = m0 + wm * 32 + mi * 16 + g;
#pragma unroll
        for (int ni = 0; ni < 4; ni++) {
            int c = n0 + wn * 32 + ni * 8 + 2 * t4;
            float b0 = Wb[c], b1 = Wb[c + 1];
            float v0 = C[mi][ni][0] + b0, v1 = C[mi][ni][1] + b1;
            float v2 = C[mi][ni][2] + b0, v3 = C[mi][ni][3] + b1;
            hid[r * HIDC + c] = v0;
            hid[r * HIDC + c + 1] = v1;
            hid[(r + 8) * HIDC + c] = v2;
            hid[(r + 8) * HIDC + c + 1] = v3;
            ls[ni * 2]     += v0 + v2;  lq[ni * 2]     += v0 * v0 + v2 * v2;
            ls[ni * 2 + 1] += v1 + v3;  lq[ni * 2 + 1] += v1 * v1 + v3 * v3;
        }
    }
#pragma unroll
    for (int j = 0; j < 8; j++) {
        float a = ls[j], q = lq[j];
        a += __shfl_xor_sync(0xffffffffu, a, 4);
        a += __shfl_xor_sync(0xffffffffu, a, 8);
        a += __shfl_xor_sync(0xffffffffu, a, 16);
        q += __shfl_xor_sync(0xffffffffu, q, 4);
        q += __shfl_xor_sync(0xffffffffu, q, 8);
        q += __shfl_xor_sync(0xffffffffu, q, 16);
        if (g == 0) {
            int c = wn * 32 + (j >> 1) * 8 + 2 * t4 + (j & 1);
            atomicAdd(&sS[c], a);
            atomicAdd(&sQ[c], q);
        }
    }
    __syncthreads();
    if (tid < 128) {
        atomicAdd(&d_colsum[n0 + tid], sS[tid]);
        atomicAdd(&d_colsq[n0 + tid], sQ[tid]);
    }
}

// ---------------- head: BN-finalize fused, 32 rows/block, Mw in smem ----------------
#define HROWS 32
__global__ void __launch_bounds__(256) k_head(const float* __restrict__ hid,
                       const float* __restrict__ gamma, const float* __restrict__ beta,
                       const float* __restrict__ Mw, const float* __restrict__ Mb,
                       float* __restrict__ out) {
    __shared__ float hs[HROWS][HIDC + 4];
    __shared__ float Ms[HIDC * COUTC];
    __shared__ float lg[HROWS][COUTC];
    __shared__ float mu_s[HIDC], rs_s[HIDC];
    int tid = threadIdx.x;
    int n0 = blockIdx.x * HROWS;

    {
        float m = d_colsum[tid] * (1.f / (float)NT);
        float var = d_colsq[tid] * (1.f / (float)NT) - m * m;
        mu_s[tid] = m;
        rs_s[tid] = rsqrtf(var + 1e-5f);
    }
    for (int i = tid; i < HIDC * COUTC; i += 256) Ms[i] = Mw[i];
    __syncthreads();
    for (int i = tid; i < HROWS * HIDC; i += 256) {
        int r = i >> 8, c = i & 255;
        float v = hid[(n0 + r) * HIDC + c];
        v = fmaf((v - mu_s[c]) * rs_s[c], gamma[c], beta[c]);
        hs[r][c] = fmaxf(v, 0.f);
    }
    __syncthreads();

#pragma unroll
    for (int l = 0; l < 5; l++) {
        int idx = tid + 256 * l;
        int r = idx / COUTC, j = idx % COUTC;
        float a = Mb[j];
#pragma unroll 8
        for (int c = 0; c < HIDC; c++) a = fmaf(hs[r][c], Ms[c * COUTC + j], a);
        lg[r][j] = a;
    }
    __syncthreads();

    int w = tid >> 5, lane = tid & 31;
#pragma unroll
    for (int rr = 0; rr < 4; rr++) {
        int r = w * 4 + rr;
        float v0 = (lane < COUTC) ? lg[r][lane] : -1e30f;
        float v1 = (lane + 32 < COUTC) ? lg[r][lane + 32] : -1e30f;
        float m = fmaxf(v0, v1);
#pragma unroll
        for (int off = 16; off; off >>= 1) m = fmaxf(m, __shfl_xor_sync(0xffffffffu, m, off));
        float se = 0.f;
        if (lane < COUTC) se += expf(v0 - m);
        if (lane + 32 < COUTC) se += expf(v1 - m);
#pragma unroll
        for (int off = 16; off; off >>= 1) se += __shfl_xor_sync(0xffffffffu, se, off);
        float lse = m + logf(se);
        if (lane < COUTC) out[(n0 + r) * COUTC + lane] = v0 - lse;
        if (lane + 32 < COUTC) out[(n0 + r) * COUTC + lane + 32] = v1 - lse;
    }
}

// ---------------- launch ----------------
extern "C" void kernel_launch(void* const* d_in, const int* in_sizes, int n_in,
                              void* d_out, int out_size) {
    const float* X     = (const float*)d_in[0];
    const float* La    = (const float*)d_in[1];
    const float* U     = (const float*)d_in[2];
    const float* eW1   = (const float*)d_in[3];
    const float* eb1   = (const float*)d_in[4];
    const float* eW2   = (const float*)d_in[5];
    const float* eb2   = (const float*)d_in[6];
    const float* eW3   = (const float*)d_in[7];
    const float* eb3   = (const float*)d_in[8];
    const float* gW1   = (const float*)d_in[9];
    const float* gb1   = (const float*)d_in[10];
    const float* gW2   = (const float*)d_in[11];
    const float* gb2   = (const float*)d_in[12];
    const float* Ww    = (const float*)d_in[13];
    const float* Wb    = (const float*)d_in[14];
    const float* gamma = (const float*)d_in[15];
    const float* beta  = (const float*)d_in[16];
    const float* Mw    = (const float*)d_in[17];
    const float* Mb    = (const float*)d_in[18];

    float* out_logits = (float*)d_out;
    float* out_hidden = (float*)d_out + (size_t)NT * COUTC;

    cudaFuncSetAttribute(k_gemmT3, cudaFuncAttributeMaxDynamicSharedMemorySize, SMEM_G);
    cudaFuncSetAttribute(k_gemmH3, cudaFuncAttributeMaxDynamicSharedMemorySize, SMEM_G);

    k_zero<<<(KT * CINC + 255) / 256, 256>>>();
    k_table<<<dim3(TGRID / 128, EE), 128>>>(eW1, eb1, eW2, eb2, eW3, eb3);
    k_gemmT3<<<dim3(4, 4, 32), 256, SMEM_G>>>(U, X);
    k_gemmP<<<dim3(4, 7, 4), 256>>>(Ww);
    k_gemmH3<<<dim3(128, 2), 256, SMEM_G>>>(U, La, gW1, gb1, gW2, gb2, Wb, out_hidden);
    k_head<<<NT / HROWS, 256>>>(out_hidden, gamma, beta, Mw, Mb, out_logits);
}

// round 6
// speedup vs baseline: 1.0715x; 1.0715x over previous
#include <cuda_runtime.h>

#define NT    8192
#define KT    200
#define CINC  512
#define HIDC  256
#define COUTC 40
#define EE    5
#define MHD   64
#define TGRID 4096
#define TBL_LO (-8.0f)
#define TBL_HI ( 8.0f)
#define PITCH 136
#define SMEM_GEMM (4 * 2 * 16 * PITCH * 4)   // 69632 B

// ---------------- scratch ----------------
__device__ float d_ftable[EE * TGRID];
__device__ float d_Vsum[KT];
__device__ float d_Tm[KT * CINC];       // T = U^T X   [200 x 512]
__device__ float d_P[KT * HIDC];        // P = T @ Ww  [200 x 256]
__device__ float d_colsum[HIDC], d_colsq[HIDC];

__device__ __forceinline__ unsigned f2tf32(float x) {
    unsigned r;
    asm("cvt.rna.tf32.f32 %0, %1;" : "=r"(r) : "f"(x));
    return r;
}

__device__ __forceinline__ void mma_tf32(float* c, const unsigned* a, const unsigned* b) {
    asm volatile(
        "mma.sync.aligned.m16n8k8.row.col.f32.tf32.tf32.f32 "
        "{%0,%1,%2,%3},{%4,%5,%6,%7},{%8,%9},{%0,%1,%2,%3};"
        : "+f"(c[0]), "+f"(c[1]), "+f"(c[2]), "+f"(c[3])
        : "r"(a[0]), "r"(a[1]), "r"(a[2]), "r"(a[3]), "r"(b[0]), "r"(b[1]));
}

// ---------------- zero accumulators ----------------
__global__ void k_zero() {
    int i = blockIdx.x * blockDim.x + threadIdx.x;
    if (i < KT * CINC) d_Tm[i] = 0.f;
    if (i < KT * HIDC) d_P[i] = 0.f;
    if (i < KT) d_Vsum[i] = 0.f;
    if (i < HIDC) { d_colsum[i] = 0.f; d_colsq[i] = 0.f; }
}

// ---------------- per-expert PWL tables ----------------
__global__ void k_table(const float* __restrict__ eW1, const float* __restrict__ eb1,
                        const float* __restrict__ eW2, const float* __restrict__ eb2,
                        const float* __restrict__ eW3, const float* __restrict__ eb3) {
    int e = blockIdx.y;
    __shared__ float W2s[MHD * MHD];
    __shared__ float W1s[MHD], b1s[MHD], b2s[MHD], W3s[MHD];
    for (int i = threadIdx.x; i < MHD * MHD; i += blockDim.x) W2s[i] = eW2[e * MHD * MHD + i];
    if (threadIdx.x < MHD) {
        W1s[threadIdx.x] = eW1[e * MHD + threadIdx.x];
        b1s[threadIdx.x] = eb1[e * MHD + threadIdx.x];
        b2s[threadIdx.x] = eb2[e * MHD + threadIdx.x];
        W3s[threadIdx.x] = eW3[e * MHD + threadIdx.x];
    }
    __syncthreads();

    int t = blockIdx.x * blockDim.x + threadIdx.x;
    float x = TBL_LO + (TBL_HI - TBL_LO) * ((float)t / (float)(TGRID - 1));

    float h1[MHD];
#pragma unroll
    for (int h = 0; h < MHD; h++) h1[h] = fmaxf(fmaf(x, W1s[h], b1s[h]), 0.f);

    float v = eb3[e];
    for (int j = 0; j < MHD; j += 4) {
        float a0 = b2s[j], a1 = b2s[j + 1], a2 = b2s[j + 2], a3 = b2s[j + 3];
#pragma unroll
        for (int h = 0; h < MHD; h++) {
            float hv = h1[h];
            float4 w = *(const float4*)&W2s[h * MHD + j];
            a0 = fmaf(hv, w.x, a0);
            a1 = fmaf(hv, w.y, a1);
            a2 = fmaf(hv, w.z, a2);
            a3 = fmaf(hv, w.w, a3);
        }
        v = fmaf(fmaxf(a0, 0.f), W3s[j],     v);
        v = fmaf(fmaxf(a1, 0.f), W3s[j + 1], v);
        v = fmaf(fmaxf(a2, 0.f), W3s[j + 2], v);
        v = fmaf(fmaxf(a3, 0.f), W3s[j + 3], v);
    }
    d_ftable[e * TGRID + t] = v;
}

// ---------------- Vsum[col] = sum_n lerp(f_e, U[n,col]) ----------------
__global__ void k_reduceV(const float* __restrict__ U) {
    int col = threadIdx.x;
    if (col >= KT) return;
    int e = col / 40;
    const float* tbl = d_ftable + e * TGRID;
    const float scale = (float)(TGRID - 1) / (TBL_HI - TBL_LO);
    int n0 = blockIdx.x * 64;

    float sum = 0.f;
    for (int n = n0; n < n0 + 64; n++) {
        float u  = U[n * KT + col];
        float xi = (u - TBL_LO) * scale;
        xi = fminf(fmaxf(xi, 0.f), (float)(TGRID - 2) + 0.9999f);
        int   i  = (int)xi;
        float fr = xi - (float)i;
        float a = tbl[i], b = tbl[i + 1];
        sum += fmaf(fr, b - a, a);
    }
    atomicAdd(&d_Vsum[col], sum);
}

// ============ 3xtf32 GEMM: T = U^T @ X, split-K over N, ping-pong smem ============
__global__ void __launch_bounds__(256) k_gemmT3(const float* __restrict__ U,
                                                const float* __restrict__ X) {
    extern __shared__ unsigned smemb[];
    unsigned* AhB = smemb;
    unsigned* AlB = AhB + 2 * 16 * PITCH;
    unsigned* BhB = AlB + 2 * 16 * PITCH;
    unsigned* BlB = BhB + 2 * 16 * PITCH;

    int m0 = blockIdx.x * 128;
    int n0 = blockIdx.y * 128;
    int tid = threadIdx.x;
    int w = tid >> 5, lane = tid & 31, g = lane >> 2, t4 = lane & 3;
    int wm = w & 1, wn = w >> 1;
    int lr = tid >> 7, lm = tid & 127;
    int gm = m0 + lm;
    bool mok = gm < KT;
    float C[4][4][4];
#pragma unroll
    for (int i = 0; i < 4; i++)
#pragma unroll
        for (int j = 0; j < 4; j++) { C[i][j][0] = C[i][j][1] = C[i][j][2] = C[i][j][3] = 0.f; }

    float uA[8], xA[8], uB[8], xB[8];
    {
        int nbase = blockIdx.z * 512;
#pragma unroll
        for (int l = 0; l < 8; l++) {
            int r = lr + 2 * l;
            uA[l] = mok ? U[(nbase + r) * KT + gm] : 0.f;
            xA[l] = X[(nbase + r) * CINC + n0 + lm];
        }
#pragma unroll
        for (int l = 0; l < 8; l++) {
            int r = lr + 2 * l;
            unsigned hi = f2tf32(uA[l]);
            AhB[r * PITCH + lm] = hi;
            AlB[r * PITCH + lm] = f2tf32(uA[l] - __uint_as_float(hi));
            unsigned xh = f2tf32(xA[l]);
            BhB[r * PITCH + lm] = xh;
            BlB[r * PITCH + lm] = f2tf32(xA[l] - __uint_as_float(xh));
        }
    }
    __syncthreads();

    for (int kt = 0; kt < 32; kt++) {
        int p = kt & 1;
        const unsigned* AhP = AhB + p * 16 * PITCH;
        const unsigned* AlP = AlB + p * 16 * PITCH;
        const unsigned* BhP = BhB + p * 16 * PITCH;
        const unsigned* BlP = BlB + p * 16 * PITCH;
        if (kt < 31) {
            int nbase = blockIdx.z * 512 + (kt + 1) * 16;
#pragma unroll
            for (int l = 0; l < 8; l++) {
                int r = lr + 2 * l;
                uB[l] = mok ? U[(nbase + r) * KT + gm] : 0.f;
                xB[l] = X[(nbase + r) * CINC + n0 + lm];
            }
        }
#pragma unroll
        for (int ks = 0; ks < 16; ks += 8) {
            unsigned ah[4][4], al[4][4], bh[4][2], bl[4][2];
#pragma unroll
            for (int mi = 0; mi < 4; mi++) {
                int rm = wm * 64 + mi * 16;
                ah[mi][0] = AhP[(ks + t4) * PITCH + rm + g];     ah[mi][1] = AhP[(ks + t4) * PITCH + rm + g + 8];
                ah[mi][2] = AhP[(ks + t4 + 4) * PITCH + rm + g]; ah[mi][3] = AhP[(ks + t4 + 4) * PITCH + rm + g + 8];
                al[mi][0] = AlP[(ks + t4) * PITCH + rm + g];     al[mi][1] = AlP[(ks + t4) * PITCH + rm + g + 8];
                al[mi][2] = AlP[(ks + t4 + 4) * PITCH + rm + g]; al[mi][3] = AlP[(ks + t4 + 4) * PITCH + rm + g + 8];
            }
#pragma unroll
            for (int ni = 0; ni < 4; ni++) {
                int cn = wn * 32 + ni * 8;
                bh[ni][0] = BhP[(ks + t4) * PITCH + cn + g]; bh[ni][1] = BhP[(ks + t4 + 4) * PITCH + cn + g];
                bl[ni][0] = BlP[(ks + t4) * PITCH + cn + g]; bl[ni][1] = BlP[(ks + t4 + 4) * PITCH + cn + g];
            }
#pragma unroll
            for (int mi = 0; mi < 4; mi++)
#pragma unroll
                for (int ni = 0; ni < 4; ni++) {
                    mma_tf32(C[mi][ni], ah[mi], bl[ni]);
                    mma_tf32(C[mi][ni], al[mi], bh[ni]);
                    mma_tf32(C[mi][ni], ah[mi], bh[ni]);
                }
        }
        if (kt < 31) {
            unsigned* AhQ = AhB + (p ^ 1) * 16 * PITCH;
            unsigned* AlQ = AlB + (p ^ 1) * 16 * PITCH;
            unsigned* BhQ = BhB + (p ^ 1) * 16 * PITCH;
            unsigned* BlQ = BlB + (p ^ 1) * 16 * PITCH;
#pragma unroll
            for (int l = 0; l < 8; l++) {
                int r = lr + 2 * l;
                unsigned hi = f2tf32(uB[l]);
                AhQ[r * PITCH + lm] = hi;
                AlQ[r * PITCH + lm] = f2tf32(uB[l] - __uint_as_float(hi));
                unsigned xh = f2tf32(xB[l]);
                BhQ[r * PITCH + lm] = xh;
                BlQ[r * PITCH + lm] = f2tf32(xB[l] - __uint_as_float(xh));
            }
        }
        __syncthreads();
    }
#pragma unroll
    for (int mi = 0; mi < 4; mi++) {
        int r = m0 + wm * 64 + mi * 16 + g;
#pragma unroll
        for (int ni = 0; ni < 4; ni++) {
            int c = n0 + wn * 32 + ni * 8 + 2 * t4;
            if (r < KT) {
                atomicAdd(&d_Tm[r * CINC + c],     C[mi][ni][0]);
                atomicAdd(&d_Tm[r * CINC + c + 1], C[mi][ni][1]);
            }
            if (r + 8 < KT) {
                atomicAdd(&d_Tm[(r + 8) * CINC + c],     C[mi][ni][2]);
                atomicAdd(&d_Tm[(r + 8) * CINC + c + 1], C[mi][ni][3]);
            }
        }
    }
}

// ============ P = T @ Ww  [200 x 256]  — 64x64 tiles, 4x4 reg tiling ============
// grid (4 Ntiles, 4 Mtiles, 4 Ksplit of 128), block 256 (16x16)
__global__ void __launch_bounds__(256) k_gemmP(const float* __restrict__ Ww) {
    __shared__ float Ast[16][68];   // [k][m] transposed
    __shared__ float Bs[16][68];    // [k][n]
    int n0 = blockIdx.x * 64;
    int m0 = blockIdx.y * 64;
    int k0 = blockIdx.z * 128;
    int tid = threadIdx.x;
    int tm = tid >> 4, tc = tid & 15;
    float acc[4][4] = {};

    for (int kc = 0; kc < 128; kc += 16) {
        // load A: 64 rows x 16 k, store transposed [k][m]
#pragma unroll
        for (int l = 0; l < 4; l++) {
            int idx = tid + 256 * l;
            int r = idx >> 4, kk = idx & 15;
            Ast[kk][r] = (m0 + r < KT) ? d_Tm[(m0 + r) * CINC + k0 + kc + kk] : 0.f;
        }
        // load B: 16 k x 64 n
#pragma unroll
        for (int l = 0; l < 4; l++) {
            int idx = tid + 256 * l;
            int kk = idx >> 6, n = idx & 63;
            Bs[kk][n] = Ww[(k0 + kc + kk) * HIDC + n0 + n];
        }
        __syncthreads();
#pragma unroll
        for (int kk = 0; kk < 16; kk++) {
            float4 av = *(const float4*)&Ast[kk][tm * 4];
            float4 bv = *(const float4*)&Bs[kk][tc * 4];
            float a[4] = {av.x, av.y, av.z, av.w};
            float b[4] = {bv.x, bv.y, bv.z, bv.w};
#pragma unroll
            for (int i = 0; i < 4; i++)
#pragma unroll
                for (int j = 0; j < 4; j++)
                    acc[i][j] = fmaf(a[i], b[j], acc[i][j]);
        }
        __syncthreads();
    }
#pragma unroll
    for (int i = 0; i < 4; i++) {
        int r = m0 + tm * 4 + i;
        if (r < KT)
#pragma unroll
            for (int j = 0; j < 4; j++)
                atomicAdd(&d_P[r * HIDC + n0 + tc * 4 + j], acc[i][j]);
    }
}

// ============ hidden = (U*s)@P + Wb, 3xtf32, gate fused, BN fused, ping-pong ============
__global__ void __launch_bounds__(256) k_gemmH3(const float* __restrict__ U,
                                                const float* __restrict__ La,
                                                const float* __restrict__ gW1, const float* __restrict__ gb1,
                                                const float* __restrict__ gW2, const float* __restrict__ gb2,
                                                const float* __restrict__ Wb,
                                                float* __restrict__ hid) {
    extern __shared__ unsigned smemb[];
    unsigned* AhB = smemb;
    unsigned* AlB = AhB + 2 * 16 * PITCH;
    unsigned* BhB = AlB + 2 * 16 * PITCH;
    unsigned* BlB = BhB + 2 * 16 * PITCH;
    __shared__ float sS[128], sQ[128];
    __shared__ float s_sm[KT];
    __shared__ float stats[EE], gsh[EE];

    int m0 = blockIdx.x * 128;
    int n0 = blockIdx.y * 128;
    int tid = threadIdx.x;
    int w = tid >> 5, lane = tid & 31, g = lane >> 2, t4 = lane & 3;
    int wm = w & 1, wn = w >> 1;
    int am = tid >> 4, ak = tid & 15;
    int br = tid >> 7, bm = tid & 127;

    if (tid < 128) { sS[tid] = 0.f; sQ[tid] = 0.f; }
    if (tid < EE) {
        float s = 0.f;
        for (int i = 0; i < 40; i++) s += La[tid * 40 + i];
        stats[tid] = s * (1.f / 40.f);
    }
    __syncthreads();
    if (tid == 0) {
        float h[EE], g2[EE];
        for (int j = 0; j < EE; j++) {
            float a = gb1[j];
            for (int i = 0; i < EE; i++) a = fmaf(stats[i], gW1[i * EE + j], a);
            h[j] = fmaxf(a, 0.f);
        }
        for (int j = 0; j < EE; j++) {
            float a = gb2[j];
            for (int i = 0; i < EE; i++) a = fmaf(h[i], gW2[i * EE + j], a);
            g2[j] = a;
        }
        float m = g2[0];
        for (int j = 1; j < EE; j++) m = fmaxf(m, g2[j]);
        float se = 0.f;
        for (int j = 0; j < EE; j++) { g2[j] = expf(g2[j] - m); se += g2[j]; }
        for (int j = 0; j < EE; j++) gsh[j] = g2[j] / se;
    }
    __syncthreads();
    if (tid < KT) s_sm[tid] = gsh[tid / 40] * d_Vsum[tid] * (1.f / (float)NT);
    __syncthreads();

    float C[4][4][4];
#pragma unroll
    for (int i = 0; i < 4; i++)
#pragma unroll
        for (int j = 0; j < 4; j++) { C[i][j][0] = C[i][j][1] = C[i][j][2] = C[i][j][3] = 0.f; }

    float aA[8], bA[8], aB[8], bB[8];
    {
#pragma unroll
        for (int l = 0; l < 8; l++) {
            int m = am + 16 * l, kk = ak;
            aA[l] = (kk < KT) ? U[(m0 + m) * KT + kk] * s_sm[kk] : 0.f;
            int r = br + 2 * l;
            bA[l] = (r < KT) ? d_P[r * HIDC + n0 + bm] : 0.f;
        }
#pragma unroll
        for (int l = 0; l < 8; l++) {
            int m = am + 16 * l;
            unsigned hi = f2tf32(aA[l]);
            AhB[ak * PITCH + m] = hi;
            AlB[ak * PITCH + m] = f2tf32(aA[l] - __uint_as_float(hi));
            int r = br + 2 * l;
            unsigned xh = f2tf32(bA[l]);
            BhB[r * PITCH + bm] = xh;
            BlB[r * PITCH + bm] = f2tf32(bA[l] - __uint_as_float(xh));
        }
    }
    __syncthreads();

    for (int kt = 0; kt < 13; kt++) {
        int p = kt & 1;
        const unsigned* AhP = AhB + p * 16 * PITCH;
        const unsigned* AlP = AlB + p * 16 * PITCH;
        const unsigned* BhP = BhB + p * 16 * PITCH;
        const unsigned* BlP = BlB + p * 16 * PITCH;
        if (kt < 12) {
            int kb2 = (kt + 1) * 16;
#pragma unroll
            for (int l = 0; l < 8; l++) {
                int m = am + 16 * l, kk = kb2 + ak;
                aB[l] = (kk < KT) ? U[(m0 + m) * KT + kk] * s_sm[kk] : 0.f;
                int r = kb2 + br + 2 * l;
                bB[l] = (r < KT) ? d_P[r * HIDC + n0 + bm] : 0.f;
            }
        }
#pragma unroll
        for (int ks = 0; ks < 16; ks += 8) {
            unsigned ah[4][4], al[4][4], bh[4][2], bl[4][2];
#pragma unroll
            for (int mi = 0; mi < 4; mi++) {
                int rm = wm * 64 + mi * 16;
                ah[mi][0] = AhP[(ks + t4) * PITCH + rm + g];     ah[mi][1] = AhP[(ks + t4) * PITCH + rm + g + 8];
                ah[mi][2] = AhP[(ks + t4 + 4) * PITCH + rm + g]; ah[mi][3] = AhP[(ks + t4 + 4) * PITCH + rm + g + 8];
                al[mi][0] = AlP[(ks + t4) * PITCH + rm + g];     al[mi][1] = AlP[(ks + t4) * PITCH + rm + g + 8];
                al[mi][2] = AlP[(ks + t4 + 4) * PITCH + rm + g]; al[mi][3] = AlP[(ks + t4 + 4) * PITCH + rm + g + 8];
            }
#pragma unroll
            for (int ni = 0; ni < 4; ni++) {
                int cn = wn * 32 + ni * 8;
                bh[ni][0] = BhP[(ks + t4) * PITCH + cn + g]; bh[ni][1] = BhP[(ks + t4 + 4) * PITCH + cn + g];
                bl[ni][0] = BlP[(ks + t4) * PITCH + cn + g]; bl[ni][1] = BlP[(ks + t4 + 4) * PITCH + cn + g];
            }
#pragma unroll
            for (int mi = 0; mi < 4; mi++)
#pragma unroll
                for (int ni = 0; ni < 4; ni++) {
                    mma_tf32(C[mi][ni], ah[mi], bl[ni]);
                    mma_tf32(C[mi][ni], al[mi], bh[ni]);
                    mma_tf32(C[mi][ni], ah[mi], bh[ni]);
                }
        }
        if (kt < 12) {
            unsigned* AhQ = AhB + (p ^ 1) * 16 * PITCH;
            unsigned* AlQ = AlB + (p ^ 1) * 16 * PITCH;
            unsigned* BhQ = BhB + (p ^ 1) * 16 * PITCH;
            unsigned* BlQ = BlB + (p ^ 1) * 16 * PITCH;
#pragma unroll
            for (int l = 0; l < 8; l++) {
                int m = am + 16 * l;
                unsigned hi = f2tf32(aB[l]);
                AhQ[ak * PITCH + m] = hi;
                AlQ[ak * PITCH + m] = f2tf32(aB[l] - __uint_as_float(hi));
                int r = br + 2 * l;
                unsigned xh = f2tf32(bB[l]);
                BhQ[r * PITCH + bm] = xh;
                BlQ[r * PITCH + bm] = f2tf32(bB[l] - __uint_as_float(xh));
            }
        }
        __syncthreads();
    }
    float ls[8] = {}, lq[8] = {};
#pragma unroll
    for (int mi = 0; mi < 4; mi++) {
        int r = m0 + wm * 64 + mi * 16 + g;
#pragma unroll
        for (int ni = 0; ni < 4; ni++) {
            int c = n0 + wn * 32 + ni * 8 + 2 * t4;
            float b0 = Wb[c], b1 = Wb[c + 1];
            float v0 = C[mi][ni][0] + b0, v1 = C[mi][ni][1] + b1;
            float v2 = C[mi][ni][2] + b0, v3 = C[mi][ni][3] + b1;
            hid[r * HIDC + c] = v0;
            hid[r * HIDC + c + 1] = v1;
            hid[(r + 8) * HIDC + c] = v2;
            hid[(r + 8) * HIDC + c + 1] = v3;
            ls[ni * 2]     += v0 + v2;  lq[ni * 2]     += v0 * v0 + v2 * v2;
            ls[ni * 2 + 1] += v1 + v3;  lq[ni * 2 + 1] += v1 * v1 + v3 * v3;
        }
    }
#pragma unroll
    for (int j = 0; j < 8; j++) {
        float a = ls[j], q = lq[j];
        a += __shfl_xor_sync(0xffffffffu, a, 4);
        a += __shfl_xor_sync(0xffffffffu, a, 8);
        a += __shfl_xor_sync(0xffffffffu, a, 16);
        q += __shfl_xor_sync(0xffffffffu, q, 4);
        q += __shfl_xor_sync(0xffffffffu, q, 8);
        q += __shfl_xor_sync(0xffffffffu, q, 16);
        if (g == 0) {
            int c = wn * 32 + (j >> 1) * 8 + 2 * t4 + (j & 1);
            atomicAdd(&sS[c], a);
            atomicAdd(&sQ[c], q);
        }
    }
    __syncthreads();
    if (tid < 128) {
        atomicAdd(&d_colsum[n0 + tid], sS[tid]);
        atomicAdd(&d_colsq[n0 + tid], sQ[tid]);
    }
}

// ---------------- head: BN-finalize fused, 32 rows/block, Mw in smem ----------------
#define HROWS 32
__global__ void __launch_bounds__(256) k_head(const float* __restrict__ hid,
                       const float* __restrict__ gamma, const float* __restrict__ beta,
                       const float* __restrict__ Mw, const float* __restrict__ Mb,
                       float* __restrict__ out) {
    __shared__ float hs[HROWS][HIDC + 4];
    __shared__ float Ms[HIDC * COUTC];
    __shared__ float lg[HROWS][COUTC];
    __shared__ float mu_s[HIDC], rs_s[HIDC];
    int tid = threadIdx.x;
    int n0 = blockIdx.x * HROWS;

    {
        float m = d_colsum[tid] * (1.f / (float)NT);
        float var = d_colsq[tid] * (1.f / (float)NT) - m * m;
        mu_s[tid] = m;
        rs_s[tid] = rsqrtf(var + 1e-5f);
    }
    for (int i = tid; i < HIDC * COUTC; i += 256) Ms[i] = Mw[i];
    __syncthreads();
    for (int i = tid; i < HROWS * HIDC; i += 256) {
        int r = i >> 8, c = i & 255;
        float v = hid[(n0 + r) * HIDC + c];
        v = fmaf((v - mu_s[c]) * rs_s[c], gamma[c], beta[c]);
        hs[r][c] = fmaxf(v, 0.f);
    }
    __syncthreads();

#pragma unroll
    for (int l = 0; l < 5; l++) {
        int idx = tid + 256 * l;
        int r = idx / COUTC, j = idx % COUTC;
        float a = Mb[j];
#pragma unroll 8
        for (int c = 0; c < HIDC; c++) a = fmaf(hs[r][c], Ms[c * COUTC + j], a);
        lg[r][j] = a;
    }
    __syncthreads();

    int w = tid >> 5, lane = tid & 31;
#pragma unroll
    for (int rr = 0; rr < 4; rr++) {
        int r = w * 4 + rr;
        float v0 = (lane < COUTC) ? lg[r][lane] : -1e30f;
        float v1 = (lane + 32 < COUTC) ? lg[r][lane + 32] : -1e30f;
        float m = fmaxf(v0, v1);
#pragma unroll
        for (int off = 16; off; off >>= 1) m = fmaxf(m, __shfl_xor_sync(0xffffffffu, m, off));
        float se = 0.f;
        if (lane < COUTC) se += expf(v0 - m);
        if (lane + 32 < COUTC) se += expf(v1 - m);
#pragma unroll
        for (int off = 16; off; off >>= 1) se += __shfl_xor_sync(0xffffffffu, se, off);
        float lse = m + logf(se);
        if (lane < COUTC) out[(n0 + r) * COUTC + lane] = v0 - lse;
        if (lane + 32 < COUTC) out[(n0 + r) * COUTC + lane + 32] = v1 - lse;
    }
}

// ---------------- launch ----------------
extern "C" void kernel_launch(void* const* d_in, const int* in_sizes, int n_in,
                              void* d_out, int out_size) {
    const float* X     = (const float*)d_in[0];
    const float* La    = (const float*)d_in[1];
    const float* U     = (const float*)d_in[2];
    const float* eW1   = (const float*)d_in[3];
    const float* eb1   = (const float*)d_in[4];
    const float* eW2   = (const float*)d_in[5];
    const float* eb2   = (const float*)d_in[6];
    const float* eW3   = (const float*)d_in[7];
    const float* eb3   = (const float*)d_in[8];
    const float* gW1   = (const float*)d_in[9];
    const float* gb1   = (const float*)d_in[10];
    const float* gW2   = (const float*)d_in[11];
    const float* gb2   = (const float*)d_in[12];
    const float* Ww    = (const float*)d_in[13];
    const float* Wb    = (const float*)d_in[14];
    const float* gamma = (const float*)d_in[15];
    const float* beta  = (const float*)d_in[16];
    const float* Mw    = (const float*)d_in[17];
    const float* Mb    = (const float*)d_in[18];

    float* out_logits = (float*)d_out;
    float* out_hidden = (float*)d_out + (size_t)NT * COUTC;

    cudaFuncSetAttribute(k_gemmT3, cudaFuncAttributeMaxDynamicSharedMemorySize, SMEM_GEMM);
    cudaFuncSetAttribute(k_gemmH3, cudaFuncAttributeMaxDynamicSharedMemorySize, SMEM_GEMM);

    k_zero<<<(KT * CINC + 255) / 256, 256>>>();
    k_table<<<dim3(TGRID / 128, EE), 128>>>(eW1, eb1, eW2, eb2, eW3, eb3);
    k_reduceV<<<NT / 64, 256>>>(U);
    k_gemmT3<<<dim3(2, 4, 16), 256, SMEM_GEMM>>>(U, X);
    k_gemmP<<<dim3(4, 4, 4), 256>>>(Ww);
    k_gemmH3<<<dim3(64, 2), 256, SMEM_GEMM>>>(U, La, gW1, gb1, gW2, gb2, Wb, out_hidden);
    k_head<<<NT / HROWS, 256>>>(out_hidden, gamma, beta, Mw, Mb, out_logits);
}

// round 7
// speedup vs baseline: 1.1380x; 1.0621x over previous
#include <cuda_runtime.h>

#define NT    8192
#define KT    200
#define CINC  512
#define HIDC  256
#define COUTC 40
#define EE    5
#define MHD   64
#define TGRID 4096
#define TBL_LO (-8.0f)
#define TBL_HI ( 8.0f)
#define PITCH 136
#define PKA   20

// ---------------- scratch ----------------
__device__ float d_ftable[EE * TGRID];
__device__ float d_Vsum[KT];
__device__ float d_Tm[KT * CINC];       // T = U^T X   [200 x 512]
__device__ float d_P[KT * HIDC];        // P = T @ Ww  [200 x 256]
__device__ float d_colsum[HIDC], d_colsq[HIDC];

__device__ __forceinline__ unsigned f2tf32(float x) {
    unsigned r;
    asm("cvt.rna.tf32.f32 %0, %1;" : "=r"(r) : "f"(x));
    return r;
}

__device__ __forceinline__ void mma_tf32(float* c, const unsigned* a, const unsigned* b) {
    asm volatile(
        "mma.sync.aligned.m16n8k8.row.col.f32.tf32.tf32.f32 "
        "{%0,%1,%2,%3},{%4,%5,%6,%7},{%8,%9},{%0,%1,%2,%3};"
        : "+f"(c[0]), "+f"(c[1]), "+f"(c[2]), "+f"(c[3])
        : "r"(a[0]), "r"(a[1]), "r"(a[2]), "r"(a[3]), "r"(b[0]), "r"(b[1]));
}

__device__ __forceinline__ unsigned smem_u32(const void* p) {
    return (unsigned)__cvta_generic_to_shared(p);
}
__device__ __forceinline__ void cpa16(unsigned dst, const void* src, int nbytes) {
    asm volatile("cp.async.cg.shared.global [%0], [%1], 16, %2;\n"
                 :: "r"(dst), "l"(src), "r"(nbytes));
}
#define CP_COMMIT() asm volatile("cp.async.commit_group;\n" ::: "memory")
#define CP_WAIT1()  asm volatile("cp.async.wait_group 1;\n" ::: "memory")
#define CP_WAIT0()  asm volatile("cp.async.wait_group 0;\n" ::: "memory")
#define CVT2(hi, lo, v) { hi = f2tf32(v); lo = f2tf32((v) - __uint_as_float(hi)); }

// ---------------- zero accumulators ----------------
__global__ void k_zero() {
    int i = blockIdx.x * blockDim.x + threadIdx.x;
    if (i < KT * CINC) d_Tm[i] = 0.f;
    if (i < KT * HIDC) d_P[i] = 0.f;
    if (i < KT) d_Vsum[i] = 0.f;
    if (i < HIDC) { d_colsum[i] = 0.f; d_colsq[i] = 0.f; }
}

// ---------------- per-expert PWL tables ----------------
__global__ void k_table(const float* __restrict__ eW1, const float* __restrict__ eb1,
                        const float* __restrict__ eW2, const float* __restrict__ eb2,
                        const float* __restrict__ eW3, const float* __restrict__ eb3) {
    int e = blockIdx.y;
    __shared__ float W2s[MHD * MHD];
    __shared__ float W1s[MHD], b1s[MHD], b2s[MHD], W3s[MHD];
    for (int i = threadIdx.x; i < MHD * MHD; i += blockDim.x) W2s[i] = eW2[e * MHD * MHD + i];
    if (threadIdx.x < MHD) {
        W1s[threadIdx.x] = eW1[e * MHD + threadIdx.x];
        b1s[threadIdx.x] = eb1[e * MHD + threadIdx.x];
        b2s[threadIdx.x] = eb2[e * MHD + threadIdx.x];
        W3s[threadIdx.x] = eW3[e * MHD + threadIdx.x];
    }
    __syncthreads();

    int t = blockIdx.x * blockDim.x + threadIdx.x;
    float x = TBL_LO + (TBL_HI - TBL_LO) * ((float)t / (float)(TGRID - 1));

    float h1[MHD];
#pragma unroll
    for (int h = 0; h < MHD; h++) h1[h] = fmaxf(fmaf(x, W1s[h], b1s[h]), 0.f);

    float v = eb3[e];
    for (int j = 0; j < MHD; j += 4) {
        float a0 = b2s[j], a1 = b2s[j + 1], a2 = b2s[j + 2], a3 = b2s[j + 3];
#pragma unroll
        for (int h = 0; h < MHD; h++) {
            float hv = h1[h];
            float4 w = *(const float4*)&W2s[h * MHD + j];
            a0 = fmaf(hv, w.x, a0);
            a1 = fmaf(hv, w.y, a1);
            a2 = fmaf(hv, w.z, a2);
            a3 = fmaf(hv, w.w, a3);
        }
        v = fmaf(fmaxf(a0, 0.f), W3s[j],     v);
        v = fmaf(fmaxf(a1, 0.f), W3s[j + 1], v);
        v = fmaf(fmaxf(a2, 0.f), W3s[j + 2], v);
        v = fmaf(fmaxf(a3, 0.f), W3s[j + 3], v);
    }
    d_ftable[e * TGRID + t] = v;
}

// ---------------- Vsum[col] = sum_n lerp(f_e, U[n,col]) ----------------
__global__ void k_reduceV(const float* __restrict__ U) {
    int col = threadIdx.x;
    if (col >= KT) return;
    int e = col / 40;
    const float* tbl = d_ftable + e * TGRID;
    const float scale = (float)(TGRID - 1) / (TBL_HI - TBL_LO);
    int n0 = blockIdx.x * 64;

    float sum = 0.f;
    for (int n = n0; n < n0 + 64; n++) {
        float u  = U[n * KT + col];
        float xi = (u - TBL_LO) * scale;
        xi = fminf(fmaxf(xi, 0.f), (float)(TGRID - 2) + 0.9999f);
        int   i  = (int)xi;
        float fr = xi - (float)i;
        float a = tbl[i], b = tbl[i + 1];
        sum += fmaf(fr, b - a, a);
    }
    atomicAdd(&d_Vsum[col], sum);
}

// ============ T = U^T @ X : 3xtf32, 128x128 tile, cp.async raw smem, occ 2 ============
// grid (2 Mtiles, 4 Ntiles, 32 Kchunks of 256 rows), block 256
__device__ __forceinline__ void t3_load(float* As, float* Bs, unsigned aB, unsigned bB,
                                        const float* U, const float* X,
                                        int st, int kt, int zb, int m0, int n0, int tid) {
#pragma unroll
    for (int l = 0; l < 2; l++) {
        int c = tid + 256 * l;      // 0..511 chunks
        int r = c >> 5;             // row 0..15
        int col = (c & 31) * 4;
        int nb = zb + kt * 16 + r;
        int acol = m0 + col;
        int av = (KT - acol) * 4; av = av < 0 ? 0 : (av > 16 ? 16 : av);
        cpa16(aB + (unsigned)(st * 2176 + r * PITCH + col) * 4u,
              &U[(size_t)nb * KT + acol], av);
        cpa16(bB + (unsigned)(st * 2176 + r * PITCH + col) * 4u,
              &X[(size_t)nb * CINC + n0 + col], 16);
    }
}

__global__ void __launch_bounds__(256, 2) k_gemmT3(const float* __restrict__ U,
                                                   const float* __restrict__ X) {
    extern __shared__ float smf[];
    float* As = smf;                 // [2][16][PITCH]
    float* Bs = smf + 2 * 2176;
    unsigned aB = smem_u32(As), bB = smem_u32(Bs);

    int m0 = blockIdx.x * 128;
    int n0 = blockIdx.y * 128;
    int zb = blockIdx.z * 256;
    int tid = threadIdx.x;
    int w = tid >> 5, lane = tid & 31, g = lane >> 2, t4 = lane & 3;
    int wm = w & 1, wn = w >> 1;
    float C[4][4][4];
#pragma unroll
    for (int i = 0; i < 4; i++)
#pragma unroll
        for (int j = 0; j < 4; j++) { C[i][j][0] = C[i][j][1] = C[i][j][2] = C[i][j][3] = 0.f; }

    t3_load(As, Bs, aB, bB, U, X, 0, 0, zb, m0, n0, tid);
    CP_COMMIT();

    for (int kt = 0; kt < 16; kt++) {
        if (kt < 15) {
            t3_load(As, Bs, aB, bB, U, X, (kt + 1) & 1, kt + 1, zb, m0, n0, tid);
            CP_COMMIT();
            CP_WAIT1();
        } else {
            CP_WAIT0();
        }
        __syncthreads();
        const float* AsP = As + (kt & 1) * 2176;
        const float* BsP = Bs + (kt & 1) * 2176;
#pragma unroll
        for (int ks = 0; ks < 16; ks += 8) {
            unsigned bh[4][2], bl[4][2];
#pragma unroll
            for (int ni = 0; ni < 4; ni++) {
                int cn = wn * 32 + ni * 8;
                float b0 = BsP[(ks + t4) * PITCH + cn + g];
                float b1 = BsP[(ks + t4 + 4) * PITCH + cn + g];
                CVT2(bh[ni][0], bl[ni][0], b0);
                CVT2(bh[ni][1], bl[ni][1], b1);
            }
#pragma unroll
            for (int mi = 0; mi < 4; mi++) {
                int rm = wm * 64 + mi * 16;
                float a0 = AsP[(ks + t4) * PITCH + rm + g];
                float a1 = AsP[(ks + t4) * PITCH + rm + g + 8];
                float a2 = AsP[(ks + t4 + 4) * PITCH + rm + g];
                float a3 = AsP[(ks + t4 + 4) * PITCH + rm + g + 8];
                unsigned ah[4], al[4];
                CVT2(ah[0], al[0], a0);
                CVT2(ah[1], al[1], a1);
                CVT2(ah[2], al[2], a2);
                CVT2(ah[3], al[3], a3);
#pragma unroll
                for (int ni = 0; ni < 4; ni++) {
                    mma_tf32(C[mi][ni], ah, bl[ni]);
                    mma_tf32(C[mi][ni], al, bh[ni]);
                    mma_tf32(C[mi][ni], ah, bh[ni]);
                }
            }
        }
        __syncthreads();
    }
#pragma unroll
    for (int mi = 0; mi < 4; mi++) {
        int r = m0 + wm * 64 + mi * 16 + g;
#pragma unroll
        for (int ni = 0; ni < 4; ni++) {
            int c = n0 + wn * 32 + ni * 8 + 2 * t4;
            if (r < KT) {
                atomicAdd(&d_Tm[r * CINC + c],     C[mi][ni][0]);
                atomicAdd(&d_Tm[r * CINC + c + 1], C[mi][ni][1]);
            }
            if (r + 8 < KT) {
                atomicAdd(&d_Tm[(r + 8) * CINC + c],     C[mi][ni][2]);
                atomicAdd(&d_Tm[(r + 8) * CINC + c + 1], C[mi][ni][3]);
            }
        }
    }
}

// ============ P = T @ Ww  [200 x 256]  — 64x64 tiles, 4x4 reg, split-K 8 ============
__global__ void __launch_bounds__(256) k_gemmP(const float* __restrict__ Ww) {
    __shared__ float Ast[16][68];
    __shared__ float Bs[16][68];
    int n0 = blockIdx.x * 64;
    int m0 = blockIdx.y * 64;
    int k0 = blockIdx.z * 64;
    int tid = threadIdx.x;
    int tm = tid >> 4, tc = tid & 15;
    float acc[4][4] = {};

    for (int kc = 0; kc < 64; kc += 16) {
#pragma unroll
        for (int l = 0; l < 4; l++) {
            int idx = tid + 256 * l;
            int r = idx >> 4, kk = idx & 15;
            Ast[kk][r] = (m0 + r < KT) ? d_Tm[(m0 + r) * CINC + k0 + kc + kk] : 0.f;
        }
#pragma unroll
        for (int l = 0; l < 4; l++) {
            int idx = tid + 256 * l;
            int kk = idx >> 6, n = idx & 63;
            Bs[kk][n] = Ww[(k0 + kc + kk) * HIDC + n0 + n];
        }
        __syncthreads();
#pragma unroll
        for (int kk = 0; kk < 16; kk++) {
            float4 av = *(const float4*)&Ast[kk][tm * 4];
            float4 bv = *(const float4*)&Bs[kk][tc * 4];
            float a[4] = {av.x, av.y, av.z, av.w};
            float b[4] = {bv.x, bv.y, bv.z, bv.w};
#pragma unroll
            for (int i = 0; i < 4; i++)
#pragma unroll
                for (int j = 0; j < 4; j++)
                    acc[i][j] = fmaf(a[i], b[j], acc[i][j]);
        }
        __syncthreads();
    }
#pragma unroll
    for (int i = 0; i < 4; i++) {
        int r = m0 + tm * 4 + i;
        if (r < KT)
#pragma unroll
            for (int j = 0; j < 4; j++)
                atomicAdd(&d_P[r * HIDC + n0 + tc * 4 + j], acc[i][j]);
    }
}

// ============ hidden = (U*s)@P + Wb : 64x128 tile, cp.async, occ 2, gate+BN fused ============
// grid (128 Mtiles, 2 Ntiles), block 256, warp tile 32x32
__device__ __forceinline__ void h3_load(unsigned aB, unsigned bB,
                                        const float* U,
                                        int st, int kt, int m0, int n0, int tid) {
    int kbase = kt * 16;
    {   // A: 64 rows x 16 k  (raw U, scaled later)
        int r = tid >> 2;
        int kcol = (tid & 3) * 4;
        int kk = kbase + kcol;
        int av = (KT - kk) * 4; av = av < 0 ? 0 : (av > 16 ? 16 : av);
        cpa16(aB + (unsigned)(st * 1280 + r * PKA + kcol) * 4u,
              &U[(size_t)(m0 + r) * KT + kk], av);
    }
#pragma unroll
    for (int l = 0; l < 2; l++) {   // B: 16 k-rows x 128 n
        int c = tid + 256 * l;
        int r = c >> 5;
        int col = (c & 31) * 4;
        int kk = kbase + r;
        int bv = (kk < KT) ? 16 : 0;
        cpa16(bB + (unsigned)(st * 2176 + r * PITCH + col) * 4u,
              &d_P[(size_t)kk * HIDC + n0 + col], bv);
    }
}

__global__ void __launch_bounds__(256, 2) k_gemmH3(const float* __restrict__ U,
                                                   const float* __restrict__ La,
                                                   const float* __restrict__ gW1, const float* __restrict__ gb1,
                                                   const float* __restrict__ gW2, const float* __restrict__ gb2,
                                                   const float* __restrict__ Wb,
                                                   float* __restrict__ hid) {
    extern __shared__ float smf[];
    float* As = smf;                 // [2][64][PKA]
    float* Bs = smf + 2 * 1280;      // [2][16][PITCH]
    unsigned aB = smem_u32(As), bB = smem_u32(Bs);
    __shared__ float sS[128], sQ[128];
    __shared__ float s_sm[208];
    __shared__ float stats[EE], gsh[EE];

    int m0 = blockIdx.x * 64;
    int n0 = blockIdx.y * 128;
    int tid = threadIdx.x;
    int w = tid >> 5, lane = tid & 31, g = lane >> 2, t4 = lane & 3;
    int wm = w & 1, wn = w >> 1;

    // ---- fused gate -> s_sm ----
    if (tid < 128) { sS[tid] = 0.f; sQ[tid] = 0.f; }
    if (tid < 208) s_sm[tid] = 0.f;
    if (tid < EE) {
        float s = 0.f;
        for (int i = 0; i < 40; i++) s += La[tid * 40 + i];
        stats[tid] = s * (1.f / 40.f);
    }
    __syncthreads();
    if (tid == 0) {
        float h[EE], g2[EE];
        for (int j = 0; j < EE; j++) {
            float a = gb1[j];
            for (int i = 0; i < EE; i++) a = fmaf(stats[i], gW1[i * EE + j], a);
            h[j] = fmaxf(a, 0.f);
        }
        for (int j = 0; j < EE; j++) {
            float a = gb2[j];
            for (int i = 0; i < EE; i++) a = fmaf(h[i], gW2[i * EE + j], a);
            g2[j] = a;
        }
        float m = g2[0];
        for (int j = 1; j < EE; j++) m = fmaxf(m, g2[j]);
        float se = 0.f;
        for (int j = 0; j < EE; j++) { g2[j] = expf(g2[j] - m); se += g2[j]; }
        for (int j = 0; j < EE; j++) gsh[j] = g2[j] / se;
    }
    __syncthreads();
    if (tid < KT) s_sm[tid] = gsh[tid / 40] * d_Vsum[tid] * (1.f / (float)NT);
    __syncthreads();

    float C[2][4][4];
#pragma unroll
    for (int i = 0; i < 2; i++)
#pragma unroll
        for (int j = 0; j < 4; j++) { C[i][j][0] = C[i][j][1] = C[i][j][2] = C[i][j][3] = 0.f; }

    h3_load(aB, bB, U, 0, 0, m0, n0, tid);
    CP_COMMIT();

    for (int kt = 0; kt < 13; kt++) {
        if (kt < 12) {
            h3_load(aB, bB, U, (kt + 1) & 1, kt + 1, m0, n0, tid);
            CP_COMMIT();
            CP_WAIT1();
        } else {
            CP_WAIT0();
        }
        __syncthreads();
        const float* AsP = As + (kt & 1) * 1280;
        const float* BsP = Bs + (kt & 1) * 2176;
        int kb = kt * 16;
#pragma unroll
        for (int ks = 0; ks < 16; ks += 8) {
            float sv0 = s_sm[kb + ks + t4];
            float sv1 = s_sm[kb + ks + t4 + 4];
            unsigned bh[4][2], bl[4][2];
#pragma unroll
            for (int ni = 0; ni < 4; ni++) {
                int cn = wn * 32 + ni * 8;
                float b0 = BsP[(ks + t4) * PITCH + cn + g];
                float b1 = BsP[(ks + t4 + 4) * PITCH + cn + g];
                CVT2(bh[ni][0], bl[ni][0], b0);
                CVT2(bh[ni][1], bl[ni][1], b1);
            }
#pragma unroll
            for (int mi = 0; mi < 2; mi++) {
                int rm = wm * 32 + mi * 16;
                float a0 = AsP[(rm + g) * PKA + ks + t4] * sv0;
                float a1 = AsP[(rm + g + 8) * PKA + ks + t4] * sv0;
                float a2 = AsP[(rm + g) * PKA + ks + t4 + 4] * sv1;
                float a3 = AsP[(rm + g + 8) * PKA + ks + t4 + 4] * sv1;
                unsigned ah[4], al[4];
                CVT2(ah[0], al[0], a0);
                CVT2(ah[1], al[1], a1);
                CVT2(ah[2], al[2], a2);
                CVT2(ah[3], al[3], a3);
#pragma unroll
                for (int ni = 0; ni < 4; ni++) {
                    mma_tf32(C[mi][ni], ah, bl[ni]);
                    mma_tf32(C[mi][ni], al, bh[ni]);
                    mma_tf32(C[mi][ni], ah, bh[ni]);
                }
            }
        }
        __syncthreads();
    }
    // epilogue: +Wb, store, BN partial sums
    float ls[8] = {}, lq[8] = {};
#pragma unroll
    for (int mi = 0; mi < 2; mi++) {
        int r = m0 + wm * 32 + mi * 16 + g;
#pragma unroll
        for (int ni = 0; ni < 4; ni++) {
            int c = n0 + wn * 32 + ni * 8 + 2 * t4;
            float b0 = Wb[c], b1 = Wb[c + 1];
            float v0 = C[mi][ni][0] + b0, v1 = C[mi][ni][1] + b1;
            float v2 = C[mi][ni][2] + b0, v3 = C[mi][ni][3] + b1;
            hid[r * HIDC + c] = v0;
            hid[r * HIDC + c + 1] = v1;
            hid[(r + 8) * HIDC + c] = v2;
            hid[(r + 8) * HIDC + c + 1] = v3;
            ls[ni * 2]     += v0 + v2;  lq[ni * 2]     += v0 * v0 + v2 * v2;
            ls[ni * 2 + 1] += v1 + v3;  lq[ni * 2 + 1] += v1 * v1 + v3 * v3;
        }
    }
#pragma unroll
    for (int j = 0; j < 8; j++) {
        float a = ls[j], q = lq[j];
        a += __shfl_xor_sync(0xffffffffu, a, 4);
        a += __shfl_xor_sync(0xffffffffu, a, 8);
        a += __shfl_xor_sync(0xffffffffu, a, 16);
        q += __shfl_xor_sync(0xffffffffu, q, 4);
        q += __shfl_xor_sync(0xffffffffu, q, 8);
        q += __shfl_xor_sync(0xffffffffu, q, 16);
        if (g == 0) {
            int c = wn * 32 + (j >> 1) * 8 + 2 * t4 + (j & 1);
            atomicAdd(&sS[c], a);
            atomicAdd(&sQ[c], q);
        }
    }
    __syncthreads();
    if (tid < 128) {
        atomicAdd(&d_colsum[n0 + tid], sS[tid]);
        atomicAdd(&d_colsq[n0 + tid], sQ[tid]);
    }
}

// ---------------- head: BN-finalize fused, 32 rows/block, Mw in smem ----------------
#define HROWS 32
__global__ void __launch_bounds__(256) k_head(const float* __restrict__ hid,
                       const float* __restrict__ gamma, const float* __restrict__ beta,
                       const float* __restrict__ Mw, const float* __restrict__ Mb,
                       float* __restrict__ out) {
    __shared__ float hs[HROWS][HIDC + 4];
    __shared__ float Ms[HIDC * COUTC];
    __shared__ float lg[HROWS][COUTC];
    __shared__ float mu_s[HIDC], rs_s[HIDC];
    int tid = threadIdx.x;
    int n0 = blockIdx.x * HROWS;

    {
        float m = d_colsum[tid] * (1.f / (float)NT);
        float var = d_colsq[tid] * (1.f / (float)NT) - m * m;
        mu_s[tid] = m;
        rs_s[tid] = rsqrtf(var + 1e-5f);
    }
    for (int i = tid; i < HIDC * COUTC; i += 256) Ms[i] = Mw[i];
    __syncthreads();
    for (int i = tid; i < HROWS * HIDC; i += 256) {
        int r = i >> 8, c = i & 255;
        float v = hid[(n0 + r) * HIDC + c];
        v = fmaf((v - mu_s[c]) * rs_s[c], gamma[c], beta[c]);
        hs[r][c] = fmaxf(v, 0.f);
    }
    __syncthreads();

#pragma unroll
    for (int l = 0; l < 5; l++) {
        int idx = tid + 256 * l;
        int r = idx / COUTC, j = idx % COUTC;
        float a = Mb[j];
#pragma unroll 8
        for (int c = 0; c < HIDC; c++) a = fmaf(hs[r][c], Ms[c * COUTC + j], a);
        lg[r][j] = a;
    }
    __syncthreads();

    int w = tid >> 5, lane = tid & 31;
#pragma unroll
    for (int rr = 0; rr < 4; rr++) {
        int r = w * 4 + rr;
        float v0 = (lane < COUTC) ? lg[r][lane] : -1e30f;
        float v1 = (lane + 32 < COUTC) ? lg[r][lane + 32] : -1e30f;
        float m = fmaxf(v0, v1);
#pragma unroll
        for (int off = 16; off; off >>= 1) m = fmaxf(m, __shfl_xor_sync(0xffffffffu, m, off));
        float se = 0.f;
        if (lane < COUTC) se += expf(v0 - m);
        if (lane + 32 < COUTC) se += expf(v1 - m);
#pragma unroll
        for (int off = 16; off; off >>= 1) se += __shfl_xor_sync(0xffffffffu, se, off);
        float lse = m + logf(se);
        if (lane < COUTC) out[(n0 + r) * COUTC + lane] = v0 - lse;
        if (lane + 32 < COUTC) out[(n0 + r) * COUTC + lane + 32] = v1 - lse;
    }
}

// ---------------- launch ----------------
extern "C" void kernel_launch(void* const* d_in, const int* in_sizes, int n_in,
                              void* d_out, int out_size) {
    const float* X     = (const float*)d_in[0];
    const float* La    = (const float*)d_in[1];
    const float* U     = (const float*)d_in[2];
    const float* eW1   = (const float*)d_in[3];
    const float* eb1   = (const float*)d_in[4];
    const float* eW2   = (const float*)d_in[5];
    const float* eb2   = (const float*)d_in[6];
    const float* eW3   = (const float*)d_in[7];
    const float* eb3   = (const float*)d_in[8];
    const float* gW1   = (const float*)d_in[9];
    const float* gb1   = (const float*)d_in[10];
    const float* gW2   = (const float*)d_in[11];
    const float* gb2   = (const float*)d_in[12];
    const float* Ww    = (const float*)d_in[13];
    const float* Wb    = (const float*)d_in[14];
    const float* gamma = (const float*)d_in[15];
    const float* beta  = (const float*)d_in[16];
    const float* Mw    = (const float*)d_in[17];
    const float* Mb    = (const float*)d_in[18];

    float* out_logits = (float*)d_out;
    float* out_hidden = (float*)d_out + (size_t)NT * COUTC;

    const int SMEM_T3 = 2 * 2176 * 2 * 4;            // 34816 B
    const int SMEM_H3 = (2 * 1280 + 2 * 2176) * 4;   // 27648 B

    k_zero<<<(KT * CINC + 255) / 256, 256>>>();
    k_table<<<dim3(TGRID / 128, EE), 128>>>(eW1, eb1, eW2, eb2, eW3, eb3);
    k_reduceV<<<NT / 64, 256>>>(U);
    k_gemmT3<<<dim3(2, 4, 32), 256, SMEM_T3>>>(U, X);
    k_gemmP<<<dim3(4, 4, 8), 256>>>(Ww);
    k_gemmH3<<<dim3(128, 2), 256, SMEM_H3>>>(U, La, gW1, gb1, gW2, gb2, Wb, out_hidden);
    k_head<<<NT / HROWS, 256>>>(out_hidden, gamma, beta, Mw, Mb, out_logits);
}

// round 8
// speedup vs baseline: 1.3851x; 1.2171x over previous
#include <cuda_runtime.h>

#define NT    8192
#define KT    200
#define CINC  512
#define HIDC  256
#define COUTC 40
#define EE    5
#define MHD   64
#define TGRID 4096
#define TBL_LO (-8.0f)
#define TBL_HI ( 8.0f)
#define P132  132          // smem pitch for 128-wide tiles (== 4 mod 32 -> conflict-free 2t4 rows)
#define PKA   20

// ---------------- scratch ----------------
__device__ float d_ftable[EE * TGRID];
__device__ float d_Vsum[KT];
__device__ float d_Tm[KT * CINC];       // T = U^T X   [200 x 512]
__device__ float d_P[KT * HIDC];        // P = T @ Ww  [200 x 256]
__device__ float d_colsum[HIDC], d_colsq[HIDC];

// bf16 split-2: v = hi + lo (each bf16), packed pairs along k.
// reg.lo16 = first (even-k) element, reg.hi16 = second (odd-k) element.
__device__ __forceinline__ void bsplit(unsigned& hi, unsigned& lo, float v0, float v1) {
    unsigned h;
    asm("cvt.rn.bf16x2.f32 %0, %1, %2;" : "=r"(h) : "f"(v1), "f"(v0));
    float r0 = v0 - __uint_as_float(h << 16);
    float r1 = v1 - __uint_as_float(h & 0xffff0000u);
    unsigned l;
    asm("cvt.rn.bf16x2.f32 %0, %1, %2;" : "=r"(l) : "f"(r1), "f"(r0));
    hi = h; lo = l;
}

__device__ __forceinline__ void mma_bf16(float* c, const unsigned* a, const unsigned* b) {
    asm volatile(
        "mma.sync.aligned.m16n8k16.row.col.f32.bf16.bf16.f32 "
        "{%0,%1,%2,%3},{%4,%5,%6,%7},{%8,%9},{%0,%1,%2,%3};"
        : "+f"(c[0]), "+f"(c[1]), "+f"(c[2]), "+f"(c[3])
        : "r"(a[0]), "r"(a[1]), "r"(a[2]), "r"(a[3]), "r"(b[0]), "r"(b[1]));
}

__device__ __forceinline__ unsigned smem_u32(const void* p) {
    return (unsigned)__cvta_generic_to_shared(p);
}
__device__ __forceinline__ void cpa16(unsigned dst, const void* src, int nbytes) {
    asm volatile("cp.async.cg.shared.global [%0], [%1], 16, %2;\n"
                 :: "r"(dst), "l"(src), "r"(nbytes));
}
#define CP_COMMIT() asm volatile("cp.async.commit_group;\n" ::: "memory")
#define CP_WAIT1()  asm volatile("cp.async.wait_group 1;\n" ::: "memory")
#define CP_WAIT0()  asm volatile("cp.async.wait_group 0;\n" ::: "memory")

// ---------------- zero accumulators ----------------
__global__ void k_zero() {
    int i = blockIdx.x * blockDim.x + threadIdx.x;
    if (i < KT * CINC) d_Tm[i] = 0.f;
    if (i < KT * HIDC) d_P[i] = 0.f;
    if (i < KT) d_Vsum[i] = 0.f;
    if (i < HIDC) { d_colsum[i] = 0.f; d_colsq[i] = 0.f; }
}

// ---------------- per-expert PWL tables ----------------
__global__ void k_table(const float* __restrict__ eW1, const float* __restrict__ eb1,
                        const float* __restrict__ eW2, const float* __restrict__ eb2,
                        const float* __restrict__ eW3, const float* __restrict__ eb3) {
    int e = blockIdx.y;
    __shared__ float W2s[MHD * MHD];
    __shared__ float W1s[MHD], b1s[MHD], b2s[MHD], W3s[MHD];
    for (int i = threadIdx.x; i < MHD * MHD; i += blockDim.x) W2s[i] = eW2[e * MHD * MHD + i];
    if (threadIdx.x < MHD) {
        W1s[threadIdx.x] = eW1[e * MHD + threadIdx.x];
        b1s[threadIdx.x] = eb1[e * MHD + threadIdx.x];
        b2s[threadIdx.x] = eb2[e * MHD + threadIdx.x];
        W3s[threadIdx.x] = eW3[e * MHD + threadIdx.x];
    }
    __syncthreads();

    int t = blockIdx.x * blockDim.x + threadIdx.x;
    float x = TBL_LO + (TBL_HI - TBL_LO) * ((float)t / (float)(TGRID - 1));

    float h1[MHD];
#pragma unroll
    for (int h = 0; h < MHD; h++) h1[h] = fmaxf(fmaf(x, W1s[h], b1s[h]), 0.f);

    float v = eb3[e];
    for (int j = 0; j < MHD; j += 4) {
        float a0 = b2s[j], a1 = b2s[j + 1], a2 = b2s[j + 2], a3 = b2s[j + 3];
#pragma unroll
        for (int h = 0; h < MHD; h++) {
            float hv = h1[h];
            float4 w = *(const float4*)&W2s[h * MHD + j];
            a0 = fmaf(hv, w.x, a0);
            a1 = fmaf(hv, w.y, a1);
            a2 = fmaf(hv, w.z, a2);
            a3 = fmaf(hv, w.w, a3);
        }
        v = fmaf(fmaxf(a0, 0.f), W3s[j],     v);
        v = fmaf(fmaxf(a1, 0.f), W3s[j + 1], v);
        v = fmaf(fmaxf(a2, 0.f), W3s[j + 2], v);
        v = fmaf(fmaxf(a3, 0.f), W3s[j + 3], v);
    }
    d_ftable[e * TGRID + t] = v;
}

// ---------------- Vsum[col] = sum_n lerp(f_e, U[n,col]) ----------------
__global__ void k_reduceV(const float* __restrict__ U) {
    int col = threadIdx.x;
    if (col >= KT) return;
    int e = col / 40;
    const float* tbl = d_ftable + e * TGRID;
    const float scale = (float)(TGRID - 1) / (TBL_HI - TBL_LO);
    int n0 = blockIdx.x * 64;

    float sum = 0.f;
    for (int n = n0; n < n0 + 64; n++) {
        float u  = U[n * KT + col];
        float xi = (u - TBL_LO) * scale;
        xi = fminf(fmaxf(xi, 0.f), (float)(TGRID - 2) + 0.9999f);
        int   i  = (int)xi;
        float fr = xi - (float)i;
        float a = tbl[i], b = tbl[i + 1];
        sum += fmaf(fr, b - a, a);
    }
    atomicAdd(&d_Vsum[col], sum);
}

// ============ T = U^T @ X : bf16-split3 m16n8k16, 128x128 tile, cp.async, occ 2 ============
// grid (2 Mtiles, 4 Ntiles, 32 Kchunks of 256 rows), block 256
__device__ __forceinline__ void t3_load(unsigned aB, unsigned bB,
                                        const float* U, const float* X,
                                        int st, int kt, int zb, int m0, int n0, int tid) {
#pragma unroll
    for (int l = 0; l < 2; l++) {
        int c = tid + 256 * l;
        int r = c >> 5;
        int col = (c & 31) * 4;
        int nb = zb + kt * 16 + r;
        int acol = m0 + col;
        int av = (KT - acol) * 4; av = av < 0 ? 0 : (av > 16 ? 16 : av);
        cpa16(aB + (unsigned)(st * 16 * P132 + r * P132 + col) * 4u,
              &U[(size_t)nb * KT + acol], av);
        cpa16(bB + (unsigned)(st * 16 * P132 + r * P132 + col) * 4u,
              &X[(size_t)nb * CINC + n0 + col], 16);
    }
}

__global__ void __launch_bounds__(256, 2) k_gemmT3(const float* __restrict__ U,
                                                   const float* __restrict__ X) {
    extern __shared__ float smf[];
    float* As = smf;                      // [2][16][P132]
    float* Bs = smf + 2 * 16 * P132;
    unsigned aB = smem_u32(As), bB = smem_u32(Bs);

    int m0 = blockIdx.x * 128;
    int n0 = blockIdx.y * 128;
    int zb = blockIdx.z * 256;
    int tid = threadIdx.x;
    int w = tid >> 5, lane = tid & 31, g = lane >> 2, t4 = lane & 3;
    int wm = w & 1, wn = w >> 1;
    float C[4][4][4];
#pragma unroll
    for (int i = 0; i < 4; i++)
#pragma unroll
        for (int j = 0; j < 4; j++) { C[i][j][0] = C[i][j][1] = C[i][j][2] = C[i][j][3] = 0.f; }

    t3_load(aB, bB, U, X, 0, 0, zb, m0, n0, tid);
    CP_COMMIT();

    for (int kt = 0; kt < 16; kt++) {
        if (kt < 15) {
            t3_load(aB, bB, U, X, (kt + 1) & 1, kt + 1, zb, m0, n0, tid);
            CP_COMMIT();
            CP_WAIT1();
        } else {
            CP_WAIT0();
        }
        __syncthreads();
        const float* AsP = As + (kt & 1) * 16 * P132;
        const float* BsP = Bs + (kt & 1) * 16 * P132;
        // B fragments (k16)
        unsigned bh[4][2], bl[4][2];
#pragma unroll
        for (int ni = 0; ni < 4; ni++) {
            int cn = wn * 32 + ni * 8 + g;
            bsplit(bh[ni][0], bl[ni][0], BsP[(2*t4)   * P132 + cn], BsP[(2*t4+1) * P132 + cn]);
            bsplit(bh[ni][1], bl[ni][1], BsP[(2*t4+8) * P132 + cn], BsP[(2*t4+9) * P132 + cn]);
        }
#pragma unroll
        for (int mi = 0; mi < 4; mi++) {
            int rm = wm * 64 + mi * 16 + g;
            unsigned ah[4], al[4];
            bsplit(ah[0], al[0], AsP[(2*t4)   * P132 + rm],     AsP[(2*t4+1) * P132 + rm]);
            bsplit(ah[1], al[1], AsP[(2*t4)   * P132 + rm + 8], AsP[(2*t4+1) * P132 + rm + 8]);
            bsplit(ah[2], al[2], AsP[(2*t4+8) * P132 + rm],     AsP[(2*t4+9) * P132 + rm]);
            bsplit(ah[3], al[3], AsP[(2*t4+8) * P132 + rm + 8], AsP[(2*t4+9) * P132 + rm + 8]);
#pragma unroll
            for (int ni = 0; ni < 4; ni++) {
                mma_bf16(C[mi][ni], ah, bl[ni]);
                mma_bf16(C[mi][ni], al, bh[ni]);
                mma_bf16(C[mi][ni], ah, bh[ni]);
            }
        }
        __syncthreads();
    }
#pragma unroll
    for (int mi = 0; mi < 4; mi++) {
        int r = m0 + wm * 64 + mi * 16 + g;
#pragma unroll
        for (int ni = 0; ni < 4; ni++) {
            int c = n0 + wn * 32 + ni * 8 + 2 * t4;
            if (r < KT) {
                atomicAdd(&d_Tm[r * CINC + c],     C[mi][ni][0]);
                atomicAdd(&d_Tm[r * CINC + c + 1], C[mi][ni][1]);
            }
            if (r + 8 < KT) {
                atomicAdd(&d_Tm[(r + 8) * CINC + c],     C[mi][ni][2]);
                atomicAdd(&d_Tm[(r + 8) * CINC + c + 1], C[mi][ni][3]);
            }
        }
    }
}

// ============ P = T @ Ww  [200 x 256]  — 64x64 tiles, 4x4 reg, split-K 8 ============
__global__ void __launch_bounds__(256) k_gemmP(const float* __restrict__ Ww) {
    __shared__ float Ast[16][68];
    __shared__ float Bs[16][68];
    int n0 = blockIdx.x * 64;
    int m0 = blockIdx.y * 64;
    int k0 = blockIdx.z * 64;
    int tid = threadIdx.x;
    int tm = tid >> 4, tc = tid & 15;
    float acc[4][4] = {};

    for (int kc = 0; kc < 64; kc += 16) {
#pragma unroll
        for (int l = 0; l < 4; l++) {
            int idx = tid + 256 * l;
            int r = idx >> 4, kk = idx & 15;
            Ast[kk][r] = (m0 + r < KT) ? d_Tm[(m0 + r) * CINC + k0 + kc + kk] : 0.f;
        }
#pragma unroll
        for (int l = 0; l < 4; l++) {
            int idx = tid + 256 * l;
            int kk = idx >> 6, n = idx & 63;
            Bs[kk][n] = Ww[(k0 + kc + kk) * HIDC + n0 + n];
        }
        __syncthreads();
#pragma unroll
        for (int kk = 0; kk < 16; kk++) {
            float4 av = *(const float4*)&Ast[kk][tm * 4];
            float4 bv = *(const float4*)&Bs[kk][tc * 4];
            float a[4] = {av.x, av.y, av.z, av.w};
            float b[4] = {bv.x, bv.y, bv.z, bv.w};
#pragma unroll
            for (int i = 0; i < 4; i++)
#pragma unroll
                for (int j = 0; j < 4; j++)
                    acc[i][j] = fmaf(a[i], b[j], acc[i][j]);
        }
        __syncthreads();
    }
#pragma unroll
    for (int i = 0; i < 4; i++) {
        int r = m0 + tm * 4 + i;
        if (r < KT)
#pragma unroll
            for (int j = 0; j < 4; j++)
                atomicAdd(&d_P[r * HIDC + n0 + tc * 4 + j], acc[i][j]);
    }
}

// ============ hidden = (U*s)@P + Wb : bf16-split3, 64x128 tile, cp.async, occ 2 ============
// grid (128 Mtiles, 2 Ntiles), block 256, warp tile 32x32
__device__ __forceinline__ void h3_load(unsigned aB, unsigned bB,
                                        const float* U,
                                        int st, int kt, int m0, int n0, int tid) {
    int kbase = kt * 16;
    {   // A: 64 rows x 16 k (raw U, scaled later)
        int r = tid >> 2;
        int kcol = (tid & 3) * 4;
        int kk = kbase + kcol;
        int av = (KT - kk) * 4; av = av < 0 ? 0 : (av > 16 ? 16 : av);
        cpa16(aB + (unsigned)(st * 64 * PKA + r * PKA + kcol) * 4u,
              &U[(size_t)(m0 + r) * KT + kk], av);
    }
#pragma unroll
    for (int l = 0; l < 2; l++) {   // B: 16 k-rows x 128 n
        int c = tid + 256 * l;
        int r = c >> 5;
        int col = (c & 31) * 4;
        int kk = kbase + r;
        int bv = (kk < KT) ? 16 : 0;
        cpa16(bB + (unsigned)(st * 16 * P132 + r * P132 + col) * 4u,
              &d_P[(size_t)kk * HIDC + n0 + col], bv);
    }
}

__global__ void __launch_bounds__(256, 2) k_gemmH3(const float* __restrict__ U,
                                                   const float* __restrict__ La,
                                                   const float* __restrict__ gW1, const float* __restrict__ gb1,
                                                   const float* __restrict__ gW2, const float* __restrict__ gb2,
                                                   const float* __restrict__ Wb,
                                                   float* __restrict__ hid) {
    extern __shared__ float smf[];
    float* As = smf;                      // [2][64][PKA]
    float* Bs = smf + 2 * 64 * PKA;       // [2][16][P132]
    unsigned aB = smem_u32(As), bB = smem_u32(Bs);
    __shared__ float sS[128], sQ[128];
    __shared__ float s_sm[224];
    __shared__ float stats[EE], gsh[EE];

    int m0 = blockIdx.x * 64;
    int n0 = blockIdx.y * 128;
    int tid = threadIdx.x;
    int w = tid >> 5, lane = tid & 31, g = lane >> 2, t4 = lane & 3;
    int wm = w & 1, wn = w >> 1;

    // ---- fused gate -> s_sm ----
    if (tid < 128) { sS[tid] = 0.f; sQ[tid] = 0.f; }
    if (tid < 224) s_sm[tid] = 0.f;
    if (tid < EE) {
        float s = 0.f;
        for (int i = 0; i < 40; i++) s += La[tid * 40 + i];
        stats[tid] = s * (1.f / 40.f);
    }
    __syncthreads();
    if (tid == 0) {
        float h[EE], g2[EE];
        for (int j = 0; j < EE; j++) {
            float a = gb1[j];
            for (int i = 0; i < EE; i++) a = fmaf(stats[i], gW1[i * EE + j], a);
            h[j] = fmaxf(a, 0.f);
        }
        for (int j = 0; j < EE; j++) {
            float a = gb2[j];
            for (int i = 0; i < EE; i++) a = fmaf(h[i], gW2[i * EE + j], a);
            g2[j] = a;
        }
        float m = g2[0];
        for (int j = 1; j < EE; j++) m = fmaxf(m, g2[j]);
        float se = 0.f;
        for (int j = 0; j < EE; j++) { g2[j] = expf(g2[j] - m); se += g2[j]; }
        for (int j = 0; j < EE; j++) gsh[j] = g2[j] / se;
    }
    __syncthreads();
    if (tid < KT) s_sm[tid] = gsh[tid / 40] * d_Vsum[tid] * (1.f / (float)NT);
    __syncthreads();

    float C[2][4][4];
#pragma unroll
    for (int i = 0; i < 2; i++)
#pragma unroll
        for (int j = 0; j < 4; j++) { C[i][j][0] = C[i][j][1] = C[i][j][2] = C[i][j][3] = 0.f; }

    h3_load(aB, bB, U, 0, 0, m0, n0, tid);
    CP_COMMIT();

    for (int kt = 0; kt < 13; kt++) {
        if (kt < 12) {
            h3_load(aB, bB, U, (kt + 1) & 1, kt + 1, m0, n0, tid);
            CP_COMMIT();
            CP_WAIT1();
        } else {
            CP_WAIT0();
        }
        __syncthreads();
        const float* AsP = As + (kt & 1) * 64 * PKA;
        const float* BsP = Bs + (kt & 1) * 16 * P132;
        int kb = kt * 16;
        float sv0 = s_sm[kb + 2*t4],     sv1 = s_sm[kb + 2*t4 + 1];
        float sv2 = s_sm[kb + 2*t4 + 8], sv3 = s_sm[kb + 2*t4 + 9];
        unsigned bh[4][2], bl[4][2];
#pragma unroll
        for (int ni = 0; ni < 4; ni++) {
            int cn = wn * 32 + ni * 8 + g;
            bsplit(bh[ni][0], bl[ni][0], BsP[(2*t4)   * P132 + cn], BsP[(2*t4+1) * P132 + cn]);
            bsplit(bh[ni][1], bl[ni][1], BsP[(2*t4+8) * P132 + cn], BsP[(2*t4+9) * P132 + cn]);
        }
#pragma unroll
        for (int mi = 0; mi < 2; mi++) {
            int rm = wm * 32 + mi * 16 + g;
            unsigned ah[4], al[4];
            float2 p0 = *(const float2*)&AsP[rm       * PKA + 2*t4];
            float2 p1 = *(const float2*)&AsP[(rm + 8) * PKA + 2*t4];
            float2 p2 = *(const float2*)&AsP[rm       * PKA + 2*t4 + 8];
            float2 p3 = *(const float2*)&AsP[(rm + 8) * PKA + 2*t4 + 8];
            bsplit(ah[0], al[0], p0.x * sv0, p0.y * sv1);
            bsplit(ah[1], al[1], p1.x * sv0, p1.y * sv1);
            bsplit(ah[2], al[2], p2.x * sv2, p2.y * sv3);
            bsplit(ah[3], al[3], p3.x * sv2, p3.y * sv3);
#pragma unroll
            for (int ni = 0; ni < 4; ni++) {
                mma_bf16(C[mi][ni], ah, bl[ni]);
                mma_bf16(C[mi][ni], al, bh[ni]);
                mma_bf16(C[mi][ni], ah, bh[ni]);
            }
        }
        __syncthreads();
    }
    // epilogue: +Wb, store, BN partial sums
    float ls[8] = {}, lq[8] = {};
#pragma unroll
    for (int mi = 0; mi < 2; mi++) {
        int r = m0 + wm * 32 + mi * 16 + g;
#pragma unroll
        for (int ni = 0; ni < 4; ni++) {
            int c = n0 + wn * 32 + ni * 8 + 2 * t4;
            float b0 = Wb[c], b1 = Wb[c + 1];
            float v0 = C[mi][ni][0] + b0, v1 = C[mi][ni][1] + b1;
            float v2 = C[mi][ni][2] + b0, v3 = C[mi][ni][3] + b1;
            hid[r * HIDC + c] = v0;
            hid[r * HIDC + c + 1] = v1;
            hid[(r + 8) * HIDC + c] = v2;
            hid[(r + 8) * HIDC + c + 1] = v3;
            ls[ni * 2]     += v0 + v2;  lq[ni * 2]     += v0 * v0 + v2 * v2;
            ls[ni * 2 + 1] += v1 + v3;  lq[ni * 2 + 1] += v1 * v1 + v3 * v3;
        }
    }
#pragma unroll
    for (int j = 0; j < 8; j++) {
        float a = ls[j], q = lq[j];
        a += __shfl_xor_sync(0xffffffffu, a, 4);
        a += __shfl_xor_sync(0xffffffffu, a, 8);
        a += __shfl_xor_sync(0xffffffffu, a, 16);
        q += __shfl_xor_sync(0xffffffffu, q, 4);
        q += __shfl_xor_sync(0xffffffffu, q, 8);
        q += __shfl_xor_sync(0xffffffffu, q, 16);
        if (g == 0) {
            int c = wn * 32 + (j >> 1) * 8 + 2 * t4 + (j & 1);
            atomicAdd(&sS[c], a);
            atomicAdd(&sQ[c], q);
        }
    }
    __syncthreads();
    if (tid < 128) {
        atomicAdd(&d_colsum[n0 + tid], sS[tid]);
        atomicAdd(&d_colsq[n0 + tid], sQ[tid]);
    }
}

// ---------------- head: BN-finalize fused, 32 rows/block, Mw in smem ----------------
#define HROWS 32
__global__ void __launch_bounds__(256) k_head(const float* __restrict__ hid,
                       const float* __restrict__ gamma, const float* __restrict__ beta,
                       const float* __restrict__ Mw, const float* __restrict__ Mb,
                       float* __restrict__ out) {
    __shared__ float hs[HROWS][HIDC + 4];
    __shared__ float Ms[HIDC * COUTC];
    __shared__ float lg[HROWS][COUTC];
    __shared__ float mu_s[HIDC], rs_s[HIDC];
    int tid = threadIdx.x;
    int n0 = blockIdx.x * HROWS;

    {
        float m = d_colsum[tid] * (1.f / (float)NT);
        float var = d_colsq[tid] * (1.f / (float)NT) - m * m;
        mu_s[tid] = m;
        rs_s[tid] = rsqrtf(var + 1e-5f);
    }
    for (int i = tid; i < HIDC * COUTC; i += 256) Ms[i] = Mw[i];
    __syncthreads();
    for (int i = tid; i < HROWS * HIDC; i += 256) {
        int r = i >> 8, c = i & 255;
        float v = hid[(n0 + r) * HIDC + c];
        v = fmaf((v - mu_s[c]) * rs_s[c], gamma[c], beta[c]);
        hs[r][c] = fmaxf(v, 0.f);
    }
    __syncthreads();

#pragma unroll
    for (int l = 0; l < 5; l++) {
        int idx = tid + 256 * l;
        int r = idx / COUTC, j = idx % COUTC;
        float a = Mb[j];
#pragma unroll 8
        for (int c = 0; c < HIDC; c++) a = fmaf(hs[r][c], Ms[c * COUTC + j], a);
        lg[r][j] = a;
    }
    __syncthreads();

    int w = tid >> 5, lane = tid & 31;
#pragma unroll
    for (int rr = 0; rr < 4; rr++) {
        int r = w * 4 + rr;
        float v0 = (lane < COUTC) ? lg[r][lane] : -1e30f;
        float v1 = (lane + 32 < COUTC) ? lg[r][lane + 32] : -1e30f;
        float m = fmaxf(v0, v1);
#pragma unroll
        for (int off = 16; off; off >>= 1) m = fmaxf(m, __shfl_xor_sync(0xffffffffu, m, off));
        float se = 0.f;
        if (lane < COUTC) se += expf(v0 - m);
        if (lane + 32 < COUTC) se += expf(v1 - m);
#pragma unroll
        for (int off = 16; off; off >>= 1) se += __shfl_xor_sync(0xffffffffu, se, off);
        float lse = m + logf(se);
        if (lane < COUTC) out[(n0 + r) * COUTC + lane] = v0 - lse;
        if (lane + 32 < COUTC) out[(n0 + r) * COUTC + lane + 32] = v1 - lse;
    }
}

// ---------------- launch ----------------
extern "C" void kernel_launch(void* const* d_in, const int* in_sizes, int n_in,
                              void* d_out, int out_size) {
    const float* X     = (const float*)d_in[0];
    const float* La    = (const float*)d_in[1];
    const float* U     = (const float*)d_in[2];
    const float* eW1   = (const float*)d_in[3];
    const float* eb1   = (const float*)d_in[4];
    const float* eW2   = (const float*)d_in[5];
    const float* eb2   = (const float*)d_in[6];
    const float* eW3   = (const float*)d_in[7];
    const float* eb3   = (const float*)d_in[8];
    const float* gW1   = (const float*)d_in[9];
    const float* gb1   = (const float*)d_in[10];
    const float* gW2   = (const float*)d_in[11];
    const float* gb2   = (const float*)d_in[12];
    const float* Ww    = (const float*)d_in[13];
    const float* Wb    = (const float*)d_in[14];
    const float* gamma = (const float*)d_in[15];
    const float* beta  = (const float*)d_in[16];
    const float* Mw    = (const float*)d_in[17];
    const float* Mb    = (const float*)d_in[18];

    float* out_logits = (float*)d_out;
    float* out_hidden = (float*)d_out + (size_t)NT * COUTC;

    const int SMEM_T3 = 2 * 16 * P132 * 2 * 4;             // 33792 B
    const int SMEM_H3 = (2 * 64 * PKA + 2 * 16 * P132) * 4; // 27136 B

    k_zero<<<(KT * CINC + 255) / 256, 256>>>();
    k_table<<<dim3(TGRID / 128, EE), 128>>>(eW1, eb1, eW2, eb2, eW3, eb3);
    k_reduceV<<<NT / 64, 256>>>(U);
    k_gemmT3<<<dim3(2, 4, 32), 256, SMEM_T3>>>(U, X);
    k_gemmP<<<dim3(4, 4, 8), 256>>>(Ww);
    k_gemmH3<<<dim3(128, 2), 256, SMEM_H3>>>(U, La, gW1, gb1, gW2, gb2, Wb, out_hidden);
    k_head<<<NT / HROWS, 256>>>(out_hidden, gamma, beta, Mw, Mb, out_logits);
}